// round 2
// baseline (speedup 1.0000x reference)
#include <cuda_runtime.h>

#define Bb   16
#define Ss   512
#define Mm   1024
#define Dd   256
#define Hh   8
#define DHd  32
#define Ff   1024
#define Vv   3000
#define Ll   6

// ---------------- scratch (device globals; allocation-free) ----------------
__device__ float g_x   [Bb*Ss*Dd];    // residual stream            [8192,256]
__device__ float g_q   [Bb*Ss*Dd];    // q buffer                   [8192,256]
__device__ float g_k   [Bb*Mm*Dd];    // k buffer (covers cross)    [16384,256]
__device__ float g_v   [Bb*Mm*Dd];    // v buffer                   [16384,256]
__device__ float g_attn[Bb*Ss*Dd];    // attention out              [8192,256]
__device__ float g_proj[Bb*Ss*Dd];    // projection out             [8192,256]
__device__ float g_ffn [Bb*Ss*Ff];    // ffn hidden                 [8192,1024]

// ---------------- embedding: x = E[seq] + pos ----------------
__global__ void embed_kernel(const int* __restrict__ seq,
                             const float* __restrict__ emb,
                             const float* __restrict__ pos,
                             float* __restrict__ x)
{
    int row = blockIdx.x;          // 0..B*S-1
    int t   = threadIdx.x;         // 0..255
    int s   = row & (Ss - 1);
    int tok = seq[row];
    x[(size_t)row*Dd + t] = emb[(size_t)tok*Dd + t] + pos[(size_t)s*Dd + t];
}

// ---------------- add-residual + LayerNorm (block per row, D=256) ----------------
__global__ void ln_kernel(const float* __restrict__ x, const float* __restrict__ r,
                          const float* __restrict__ g, const float* __restrict__ b,
                          float* __restrict__ y)
{
    __shared__ float red[256];
    int row = blockIdx.x, t = threadIdx.x;
    float v = x[(size_t)row*Dd + t];
    if (r) v += r[(size_t)row*Dd + t];
    red[t] = v; __syncthreads();
    #pragma unroll
    for (int s = 128; s > 0; s >>= 1) { if (t < s) red[t] += red[t + s]; __syncthreads(); }
    float mu = red[0] * (1.0f / Dd);
    __syncthreads();
    float dv = v - mu;
    red[t] = dv * dv; __syncthreads();
    #pragma unroll
    for (int s = 128; s > 0; s >>= 1) { if (t < s) red[t] += red[t + s]; __syncthreads(); }
    float var = red[0] * (1.0f / Dd);
    y[(size_t)row*Dd + t] = dv * rsqrtf(var + 1e-5f) * g[t] + b[t];
}

// ---------------- tiled SGEMM: C = A @ B (+bias)(+relu) ----------------
// A [M,K] row-major. TRANSB=false: B [K,N]; TRANSB=true: B [N,K] (C = A @ B^T).
// 64x64 C tile, K-tile 32, 256 threads, 4x4 microtile with STRIDED assignment
// (rows ty+16i, cols tx+16j) -> conflict-free smem access.
// M must be a multiple of 64 and K a multiple of 32 (true for all call sites);
// N is bounds-checked (V=3000).
template<bool TRANSB, bool RELU>
__global__ void gemm_kernel(const float* __restrict__ A, const float* __restrict__ Bm,
                            const float* __restrict__ bias, float* __restrict__ C,
                            int M, int N, int K)
{
    __shared__ float As[64][33];
    __shared__ float Bs[64*33];   // NN uses first 32*64 as [32][64]; NT uses [64][33]
    int tid = threadIdx.x;
    int tx = tid & 15, ty = tid >> 4;
    int m0 = blockIdx.y * 64, n0 = blockIdx.x * 64;
    float acc[4][4] = {};
    for (int k0 = 0; k0 < K; k0 += 32) {
        #pragma unroll
        for (int i = 0; i < 8; i++) {            // A tile: 2048 elems, coalesced
            int e = tid + i*256;
            int r = e >> 5, c = e & 31;
            As[r][c] = A[(size_t)(m0 + r)*K + k0 + c];
        }
        if (TRANSB) {
            #pragma unroll
            for (int i = 0; i < 8; i++) {
                int e = tid + i*256;
                int r = e >> 5, c = e & 31;
                int n = n0 + r;
                Bs[r*33 + c] = (n < N) ? Bm[(size_t)n*K + k0 + c] : 0.f;
            }
        } else {
            #pragma unroll
            for (int i = 0; i < 8; i++) {
                int e = tid + i*256;
                int r = e >> 6, c = e & 63;
                int n = n0 + c;
                Bs[r*64 + c] = (n < N) ? Bm[(size_t)(k0 + r)*N + n] : 0.f;
            }
        }
        __syncthreads();
        #pragma unroll
        for (int kk = 0; kk < 32; kk++) {
            float a[4], bv[4];
            #pragma unroll
            for (int i = 0; i < 4; i++) a[i] = As[ty + 16*i][kk];
            #pragma unroll
            for (int j = 0; j < 4; j++)
                bv[j] = TRANSB ? Bs[(tx + 16*j)*33 + kk] : Bs[kk*64 + tx + 16*j];
            #pragma unroll
            for (int i = 0; i < 4; i++)
                #pragma unroll
                for (int j = 0; j < 4; j++)
                    acc[i][j] += a[i] * bv[j];
        }
        __syncthreads();
    }
    #pragma unroll
    for (int i = 0; i < 4; i++) {
        int r = m0 + ty + 16*i;
        #pragma unroll
        for (int j = 0; j < 4; j++) {
            int c = n0 + tx + 16*j;
            if (c < N) {
                float v = acc[i][j] + (bias ? bias[c] : 0.f);
                if (RELU) v = fmaxf(v, 0.f);
                C[(size_t)r*N + c] = v;
            }
        }
    }
}

// ---------------- flash attention (fp32, DH=32) ----------------
// Q [B,Sq,D] with head h at cols h*32.. ; K,V [B,Skv,D] likewise.
// grid = (Sq/64, B*H), 256 threads (16x16), 64Q x 64K tiles, online softmax.
__global__ void attn_kernel(const float* __restrict__ Q, const float* __restrict__ K,
                            const float* __restrict__ V, float* __restrict__ O,
                            int SqL, int SkvL, int causal)
{
    __shared__ float Qs[64][33], Ks[64][33], Vs[64][33];
    __shared__ float Ps[64][65];
    int tid = threadIdx.x;
    int tx = tid & 15, ty = tid >> 4;
    int b = blockIdx.y >> 3;   // / H
    int h = blockIdx.y & 7;    // % H
    int q0 = blockIdx.x * 64;
    const float scale = 0.17677669529663687f;  // 1/sqrt(32)

    #pragma unroll
    for (int i = 0; i < 8; i++) {
        int e = tid + i*256;
        int r = e >> 5, d = e & 31;
        Qs[r][d] = Q[((size_t)(b*SqL + q0 + r))*Dd + h*DHd + d];
    }

    float mrow[4], lrow[4], o0[4], o1[4];
    #pragma unroll
    for (int i = 0; i < 4; i++) { mrow[i] = -1e30f; lrow[i] = 0.f; o0[i] = 0.f; o1[i] = 0.f; }

    int nkt = causal ? ((int)blockIdx.x + 1) : (SkvL >> 6);
    for (int kt = 0; kt < nkt; kt++) {
        int k0 = kt * 64;
        __syncthreads();   // previous Ps/Vs consumers done before overwrite
        #pragma unroll
        for (int i = 0; i < 8; i++) {
            int e = tid + i*256;
            int r = e >> 5, d = e & 31;
            size_t gi = ((size_t)(b*SkvL + k0 + r))*Dd + h*DHd + d;
            Ks[r][d] = K[gi];
            Vs[r][d] = V[gi];
        }
        __syncthreads();

        float s[4][4] = {};
        #pragma unroll
        for (int d = 0; d < 32; d++) {
            float a[4], bb[4];
            #pragma unroll
            for (int i = 0; i < 4; i++) a[i] = Qs[ty + 16*i][d];
            #pragma unroll
            for (int j = 0; j < 4; j++) bb[j] = Ks[tx + 16*j][d];
            #pragma unroll
            for (int i = 0; i < 4; i++)
                #pragma unroll
                for (int j = 0; j < 4; j++)
                    s[i][j] += a[i] * bb[j];
        }
        bool diag = causal && (kt == (int)blockIdx.x);
        #pragma unroll
        for (int i = 0; i < 4; i++) {
            int qi = q0 + ty + 16*i;
            #pragma unroll
            for (int j = 0; j < 4; j++) {
                s[i][j] *= scale;
                if (diag && (k0 + tx + 16*j > qi)) s[i][j] = -1e9f;
            }
        }
        // online softmax; row groups are 16 consecutive lanes (shfl width 16)
        #pragma unroll
        for (int i = 0; i < 4; i++) {
            float rm = fmaxf(fmaxf(s[i][0], s[i][1]), fmaxf(s[i][2], s[i][3]));
            #pragma unroll
            for (int off = 8; off > 0; off >>= 1)
                rm = fmaxf(rm, __shfl_xor_sync(0xffffffffu, rm, off, 16));
            float mn = fmaxf(mrow[i], rm);
            float alpha = expf(mrow[i] - mn);
            float rs = 0.f;
            #pragma unroll
            for (int j = 0; j < 4; j++) { s[i][j] = expf(s[i][j] - mn); rs += s[i][j]; }
            #pragma unroll
            for (int off = 8; off > 0; off >>= 1)
                rs += __shfl_xor_sync(0xffffffffu, rs, off, 16);
            lrow[i] = lrow[i]*alpha + rs;
            o0[i] *= alpha; o1[i] *= alpha;
            mrow[i] = mn;
            #pragma unroll
            for (int j = 0; j < 4; j++)
                Ps[ty + 16*i][tx + 16*j] = s[i][j];
        }
        __syncthreads();
        #pragma unroll 8
        for (int jj = 0; jj < 64; jj++) {
            float v0 = Vs[jj][tx], v1 = Vs[jj][tx + 16];
            #pragma unroll
            for (int i = 0; i < 4; i++) {
                float p = Ps[ty + 16*i][jj];
                o0[i] += p * v0; o1[i] += p * v1;
            }
        }
    }
    #pragma unroll
    for (int i = 0; i < 4; i++) {
        float inv = 1.f / lrow[i];
        size_t base = ((size_t)(b*SqL + q0 + ty + 16*i))*Dd + h*DHd;
        O[base + tx]      = o0[i] * inv;
        O[base + tx + 16] = o1[i] * inv;
    }
}

// ---------------- host orchestration ----------------
extern "C" void kernel_launch(void* const* d_in, const int* in_sizes, int n_in,
                              void* d_out, int out_size)
{
    const float* encoded = (const float*)d_in[0];
    const int*   seq     = (const int*)  d_in[1];
    const float* emb     = (const float*)d_in[2];
    const float* pos     = (const float*)d_in[3];
    const float* obias   = (const float*)d_in[4];
    const float* sa_qkv  = (const float*)d_in[5];
    const float* sa_o    = (const float*)d_in[6];
    const float* ca_q    = (const float*)d_in[7];
    const float* ca_kv   = (const float*)d_in[8];
    const float* ca_o    = (const float*)d_in[9];
    const float* ffn_w1  = (const float*)d_in[10];
    const float* ffn_b1  = (const float*)d_in[11];
    const float* ffn_w2  = (const float*)d_in[12];
    const float* ffn_b2  = (const float*)d_in[13];
    const float* ln_g    = (const float*)d_in[14];
    const float* ln_b    = (const float*)d_in[15];
    const float* fin_g   = (const float*)d_in[16];
    const float* fin_b   = (const float*)d_in[17];
    float* out = (float*)d_out;

    float *x, *q, *k, *v, *attn, *proj, *ffn;
    cudaGetSymbolAddress((void**)&x,    g_x);
    cudaGetSymbolAddress((void**)&q,    g_q);
    cudaGetSymbolAddress((void**)&k,    g_k);
    cudaGetSymbolAddress((void**)&v,    g_v);
    cudaGetSymbolAddress((void**)&attn, g_attn);
    cudaGetSymbolAddress((void**)&proj, g_proj);
    cudaGetSymbolAddress((void**)&ffn,  g_ffn);

    const int NQ = Bb * Ss;   // 8192
    const int NE = Bb * Mm;   // 16384

    dim3 gProj(Dd/64, NQ/64);        // N=256 gemms on x
    dim3 gKV  (Dd/64, NE/64);        // encoded projections
    dim3 gF1  (Ff/64, NQ/64);        // ffn up
    dim3 gF2  (Dd/64, NQ/64);        // ffn down
    dim3 gOut ((Vv + 63)/64, NQ/64); // logits
    dim3 gAttn(Ss/64, Bb*Hh);

    embed_kernel<<<NQ, 256>>>(seq, emb, pos, x);

    for (int i = 0; i < Ll; i++) {
        const float* Wq = sa_qkv + ((size_t)i*3 + 0)*Dd*Dd;
        const float* Wk = sa_qkv + ((size_t)i*3 + 1)*Dd*Dd;
        const float* Wv = sa_qkv + ((size_t)i*3 + 2)*Dd*Dd;

        // ---- self attention ----
        gemm_kernel<false,false><<<gProj, 256>>>(x, Wq, nullptr, q, NQ, Dd, Dd);
        gemm_kernel<false,false><<<gProj, 256>>>(x, Wk, nullptr, k, NQ, Dd, Dd);
        gemm_kernel<false,false><<<gProj, 256>>>(x, Wv, nullptr, v, NQ, Dd, Dd);
        attn_kernel<<<gAttn, 256>>>(q, k, v, attn, Ss, Ss, 1);
        gemm_kernel<false,false><<<gProj, 256>>>(attn, sa_o + (size_t)i*Dd*Dd,
                                                 nullptr, proj, NQ, Dd, Dd);
        ln_kernel<<<NQ, 256>>>(x, proj, ln_g + ((size_t)i*3 + 0)*Dd,
                               ln_b + ((size_t)i*3 + 0)*Dd, x);

        // ---- cross attention ----
        gemm_kernel<false,false><<<gProj, 256>>>(x, ca_q + (size_t)i*Dd*Dd,
                                                 nullptr, q, NQ, Dd, Dd);
        gemm_kernel<false,false><<<gKV, 256>>>(encoded,
                                               ca_kv + ((size_t)i*2 + 0)*Dd*Dd,
                                               nullptr, k, NE, Dd, Dd);
        gemm_kernel<false,false><<<gKV, 256>>>(encoded,
                                               ca_kv + ((size_t)i*2 + 1)*Dd*Dd,
                                               nullptr, v, NE, Dd, Dd);
        attn_kernel<<<gAttn, 256>>>(q, k, v, attn, Ss, Mm, 0);
        gemm_kernel<false,false><<<gProj, 256>>>(attn, ca_o + (size_t)i*Dd*Dd,
                                                 nullptr, proj, NQ, Dd, Dd);
        ln_kernel<<<NQ, 256>>>(x, proj, ln_g + ((size_t)i*3 + 1)*Dd,
                               ln_b + ((size_t)i*3 + 1)*Dd, x);

        // ---- FFN ----
        gemm_kernel<false,true ><<<gF1, 256>>>(x, ffn_w1 + (size_t)i*Dd*Ff,
                                               ffn_b1 + (size_t)i*Ff, ffn, NQ, Ff, Dd);
        gemm_kernel<false,false><<<gF2, 256>>>(ffn, ffn_w2 + (size_t)i*Ff*Dd,
                                               ffn_b2 + (size_t)i*Dd, proj, NQ, Dd, Ff);
        ln_kernel<<<NQ, 256>>>(x, proj, ln_g + ((size_t)i*3 + 2)*Dd,
                               ln_b + ((size_t)i*3 + 2)*Dd, x);
    }

    // final norm + shared-embedding output projection (x @ E^T + bias)
    ln_kernel<<<NQ, 256>>>(x, nullptr, fin_g, fin_b, x);
    gemm_kernel<true,false><<<gOut, 256>>>(x, emb, obias, out, NQ, Vv, Dd);
}

// round 8
// speedup vs baseline: 3.0155x; 3.0155x over previous
#include <cuda_runtime.h>
#include <cstdint>

#define Bb   16
#define Ss   512
#define Mm   1024
#define Dd   256
#define Hh   8
#define DHd  32
#define Ff   1024
#define Vv   3000
#define Ll   6

// ---------------- scratch (device globals; allocation-free) ----------------
__device__ float g_x   [Bb*Ss*Dd];
__device__ float g_q   [Bb*Ss*Dd];
__device__ float g_k   [Bb*Mm*Dd];
__device__ float g_v   [Bb*Mm*Dd];
__device__ float g_attn[Bb*Ss*Dd];
__device__ float g_proj[Bb*Ss*Dd];
__device__ float g_ffn [Bb*Ss*Ff];

// ---------------- embedding ----------------
__global__ void embed_kernel(const int* __restrict__ seq,
                             const float* __restrict__ emb,
                             const float* __restrict__ pos,
                             float* __restrict__ x)
{
    int row = blockIdx.x;
    int t   = threadIdx.x;
    int s   = row & (Ss - 1);
    int tok = seq[row];
    x[(size_t)row*Dd + t] = emb[(size_t)tok*Dd + t] + pos[(size_t)s*Dd + t];
}

// ---------------- add-residual + LayerNorm ----------------
__global__ void ln_kernel(const float* __restrict__ x, const float* __restrict__ r,
                          const float* __restrict__ g, const float* __restrict__ b,
                          float* __restrict__ y)
{
    __shared__ float red[256];
    int row = blockIdx.x, t = threadIdx.x;
    float v = x[(size_t)row*Dd + t];
    if (r) v += r[(size_t)row*Dd + t];
    red[t] = v; __syncthreads();
    #pragma unroll
    for (int s = 128; s > 0; s >>= 1) { if (t < s) red[t] += red[t + s]; __syncthreads(); }
    float mu = red[0] * (1.0f / Dd);
    __syncthreads();
    float dv = v - mu;
    red[t] = dv * dv; __syncthreads();
    #pragma unroll
    for (int s = 128; s > 0; s >>= 1) { if (t < s) red[t] += red[t + s]; __syncthreads(); }
    float var = red[0] * (1.0f / Dd);
    y[(size_t)row*Dd + t] = dv * rsqrtf(var + 1e-5f) * g[t] + b[t];
}

// ---------------- tf32 helpers ----------------
__device__ __forceinline__ uint32_t f2tf32(float x) {
    uint32_t y; asm("cvt.rna.tf32.f32 %0, %1;" : "=r"(y) : "f"(x)); return y;
}

__device__ __forceinline__ void mma_tf32(float* d, const uint32_t* a, const uint32_t* b) {
    asm volatile(
        "mma.sync.aligned.m16n8k8.row.col.f32.tf32.tf32.f32 "
        "{%0,%1,%2,%3}, {%4,%5,%6,%7}, {%8,%9}, {%0,%1,%2,%3};"
        : "+f"(d[0]), "+f"(d[1]), "+f"(d[2]), "+f"(d[3])
        : "r"(a[0]), "r"(a[1]), "r"(a[2]), "r"(a[3]), "r"(b[0]), "r"(b[1]));
}

// ---------------- tf32 tensor-core GEMM ----------------
// C = A @ B (+bias)(+relu).  A [M,K] row-major.
// TRANSB=false: B [K,N]; TRANSB=true: B [N,K] (C = A @ B^T).
// 128x128 C tile, K-tile 32, 256 threads (8 warps, 2x4), warp tile 64x32.
// M % 128 == 0 and K % 32 == 0 required (true at all call sites); N checked.
#define LDA 36      // 32 + 4 : fragment-read bank = 4*grp+th (conflict-free)
#define LDB 136     // 128 + 8: fragment-read bank = 8*th+grp (conflict-free)

template<bool TRANSB, bool RELU>
__global__ void __launch_bounds__(256)
gemm_tc(const float* __restrict__ A, const float* __restrict__ Bm,
        const float* __restrict__ bias, float* __restrict__ C,
        int M, int N, int K)
{
    __shared__ uint32_t As[128 * LDA];
    __shared__ uint32_t Bs[128 * LDA];   // NT: [128][36]; NN: [32][136] (4352 < 4608)
    int tid  = threadIdx.x;
    int warp = tid >> 5, lane = tid & 31;
    int wm = warp >> 2, wn = warp & 3;
    int grp = lane >> 2, th = lane & 3;
    int m0 = blockIdx.y * 128, n0 = blockIdx.x * 128;

    float acc[4][4][4] = {};

    for (int k0 = 0; k0 < K; k0 += 32) {
        #pragma unroll
        for (int i = 0; i < 4; i++) {
            int e = tid + i * 256;
            int r = e >> 3, c = (e & 7) * 4;
            float4 v = *(const float4*)&A[(size_t)(m0 + r) * K + k0 + c];
            uint32_t* p = &As[r * LDA + c];
            p[0] = f2tf32(v.x); p[1] = f2tf32(v.y); p[2] = f2tf32(v.z); p[3] = f2tf32(v.w);
        }
        if (TRANSB) {
            #pragma unroll
            for (int i = 0; i < 4; i++) {
                int e = tid + i * 256;
                int r = e >> 3, c = (e & 7) * 4;
                int n = n0 + r;
                float4 v = (n < N) ? *(const float4*)&Bm[(size_t)n * K + k0 + c]
                                   : make_float4(0.f, 0.f, 0.f, 0.f);
                uint32_t* p = &Bs[r * LDA + c];
                p[0] = f2tf32(v.x); p[1] = f2tf32(v.y); p[2] = f2tf32(v.z); p[3] = f2tf32(v.w);
            }
        } else {
            #pragma unroll
            for (int i = 0; i < 4; i++) {
                int e = tid + i * 256;
                int r = e >> 5, c = (e & 31) * 4;
                float4 v = *(const float4*)&Bm[(size_t)(k0 + r) * N + n0 + c];
                uint32_t* p = &Bs[r * LDB + c];
                p[0] = f2tf32(v.x); p[1] = f2tf32(v.y); p[2] = f2tf32(v.z); p[3] = f2tf32(v.w);
            }
        }
        __syncthreads();

        #pragma unroll
        for (int kk = 0; kk < 32; kk += 8) {
            uint32_t afr[4][4], bfr[4][2];
            #pragma unroll
            for (int mt = 0; mt < 4; mt++) {
                int mr = (wm * 64 + mt * 16) * LDA + kk;
                afr[mt][0] = As[mr + grp * LDA + th];
                afr[mt][1] = As[mr + (grp + 8) * LDA + th];
                afr[mt][2] = As[mr + grp * LDA + th + 4];
                afr[mt][3] = As[mr + (grp + 8) * LDA + th + 4];
            }
            #pragma unroll
            for (int nt = 0; nt < 4; nt++) {
                int nc = wn * 32 + nt * 8 + grp;
                if (TRANSB) {
                    bfr[nt][0] = Bs[nc * LDA + kk + th];
                    bfr[nt][1] = Bs[nc * LDA + kk + th + 4];
                } else {
                    bfr[nt][0] = Bs[(kk + th) * LDB + nc];
                    bfr[nt][1] = Bs[(kk + th + 4) * LDB + nc];
                }
            }
            #pragma unroll
            for (int mt = 0; mt < 4; mt++)
                #pragma unroll
                for (int nt = 0; nt < 4; nt++)
                    mma_tf32(acc[mt][nt], afr[mt], bfr[nt]);
        }
        __syncthreads();
    }

    #pragma unroll
    for (int mt = 0; mt < 4; mt++) {
        int row0 = m0 + wm * 64 + mt * 16 + grp;
        #pragma unroll
        for (int nt = 0; nt < 4; nt++) {
            int col = n0 + wn * 32 + nt * 8 + th * 2;
            float bi0 = bias ? bias[min(col, N - 1)] : 0.f;
            float bi1 = bias ? bias[min(col + 1, N - 1)] : 0.f;
            #pragma unroll
            for (int half = 0; half < 2; half++) {
                int row = row0 + half * 8;
                float v0 = acc[mt][nt][half * 2 + 0] + bi0;
                float v1 = acc[mt][nt][half * 2 + 1] + bi1;
                if (RELU) { v0 = fmaxf(v0, 0.f); v1 = fmaxf(v1, 0.f); }
                if (col < N)     C[(size_t)row * N + col]     = v0;
                if (col + 1 < N) C[(size_t)row * N + col + 1] = v1;
            }
        }
    }
}

// ---------------- tf32 tensor-core flash attention (DH=32) ----------------
// Block: 64 Q rows of one (b,h); 128 threads = 4 warps; warp w owns Q rows
// w*16..w*16+15. S = (Q*scale)·K^T and O += P·V via mma.m16n8k8.
// Smem strides: Q/K 36 (bank 4*grp+th), V 40 (bank 8*th+grp), P 68 (bank 4*grp+th)
// -> all fragment reads conflict-free. Ps rows are warp-private.
#define LDQ 36
#define LDV 40
#define LDP 68

__global__ void __launch_bounds__(128)
attn_tc(const float* __restrict__ Q, const float* __restrict__ K,
        const float* __restrict__ V, float* __restrict__ O,
        int SqL, int SkvL, int causal)
{
    __shared__ uint32_t Qs[64 * LDQ];
    __shared__ uint32_t Ks[64 * LDQ];
    __shared__ uint32_t Vs[64 * LDV];
    __shared__ uint32_t Ps[64 * LDP];
    int tid = threadIdx.x;
    int warp = tid >> 5, lane = tid & 31;
    int grp = lane >> 2, th = lane & 3;
    int b = blockIdx.y >> 3, h = blockIdx.y & 7;
    int q0 = blockIdx.x * 64;
    const float scale = 0.17677669529663687f;   // 1/sqrt(32)

    // Q tile (pre-scaled), 64x32, float4
    #pragma unroll
    for (int i = 0; i < 4; i++) {
        int e = tid + i * 128;
        int r = e >> 3, c = (e & 7) * 4;
        float4 v = *(const float4*)&Q[((size_t)(b*SqL + q0 + r))*Dd + h*DHd + c];
        uint32_t* p = &Qs[r * LDQ + c];
        p[0] = f2tf32(v.x*scale); p[1] = f2tf32(v.y*scale);
        p[2] = f2tf32(v.z*scale); p[3] = f2tf32(v.w*scale);
    }

    float m0r = -1e30f, m1r = -1e30f, l0 = 0.f, l1 = 0.f;
    float oacc[4][4] = {};
    int prow0 = (warp*16 + grp) * LDP;
    int prow1 = (warp*16 + grp + 8) * LDP;

    int nkt = causal ? ((int)blockIdx.x + 1) : (SkvL >> 6);
    for (int kt = 0; kt < nkt; kt++) {
        int k0 = kt * 64;
        __syncthreads();            // previous iter's Ks/Vs/Ps consumers done
        #pragma unroll
        for (int i = 0; i < 4; i++) {
            int e = tid + i * 128;
            int r = e >> 3, c = (e & 7) * 4;
            size_t gi = ((size_t)(b*SkvL + k0 + r))*Dd + h*DHd + c;
            float4 kv = *(const float4*)&K[gi];
            float4 vv = *(const float4*)&V[gi];
            uint32_t* pk = &Ks[r * LDQ + c];
            pk[0] = f2tf32(kv.x); pk[1] = f2tf32(kv.y); pk[2] = f2tf32(kv.z); pk[3] = f2tf32(kv.w);
            uint32_t* pv = &Vs[r * LDV + c];
            pv[0] = f2tf32(vv.x); pv[1] = f2tf32(vv.y); pv[2] = f2tf32(vv.z); pv[3] = f2tf32(vv.w);
        }
        __syncthreads();

        // ---- S = Qs @ Ks^T : warp computes 16x64 ----
        float sacc[8][4] = {};
        #pragma unroll
        for (int kk = 0; kk < 32; kk += 8) {
            uint32_t afr[4];
            int mr = (warp*16) * LDQ + kk;
            afr[0] = Qs[mr + grp * LDQ + th];
            afr[1] = Qs[mr + (grp + 8) * LDQ + th];
            afr[2] = Qs[mr + grp * LDQ + th + 4];
            afr[3] = Qs[mr + (grp + 8) * LDQ + th + 4];
            #pragma unroll
            for (int nt = 0; nt < 8; nt++) {
                uint32_t bfr[2];
                int nc = nt * 8 + grp;
                bfr[0] = Ks[nc * LDQ + kk + th];
                bfr[1] = Ks[nc * LDQ + kk + th + 4];
                mma_tf32(sacc[nt], afr, bfr);
            }
        }

        // ---- causal mask on the diagonal tile ----
        if (causal && kt == (int)blockIdx.x) {
            int qg = q0 + warp*16 + grp;
            #pragma unroll
            for (int nt = 0; nt < 8; nt++) {
                int kv0 = k0 + nt*8 + 2*th;
                if (kv0     > qg)     sacc[nt][0] = -1e9f;
                if (kv0 + 1 > qg)     sacc[nt][1] = -1e9f;
                if (kv0     > qg + 8) sacc[nt][2] = -1e9f;
                if (kv0 + 1 > qg + 8) sacc[nt][3] = -1e9f;
            }
        }

        // ---- online softmax (rows grp and grp+8; 4-lane row groups) ----
        float rm0 = -1e30f, rm1 = -1e30f;
        #pragma unroll
        for (int nt = 0; nt < 8; nt++) {
            rm0 = fmaxf(rm0, fmaxf(sacc[nt][0], sacc[nt][1]));
            rm1 = fmaxf(rm1, fmaxf(sacc[nt][2], sacc[nt][3]));
        }
        rm0 = fmaxf(rm0, __shfl_xor_sync(0xffffffffu, rm0, 1));
        rm0 = fmaxf(rm0, __shfl_xor_sync(0xffffffffu, rm0, 2));
        rm1 = fmaxf(rm1, __shfl_xor_sync(0xffffffffu, rm1, 1));
        rm1 = fmaxf(rm1, __shfl_xor_sync(0xffffffffu, rm1, 2));
        float mn0 = fmaxf(m0r, rm0), mn1 = fmaxf(m1r, rm1);
        float a0 = __expf(m0r - mn0), a1 = __expf(m1r - mn1);
        float rs0 = 0.f, rs1 = 0.f;
        #pragma unroll
        for (int nt = 0; nt < 8; nt++) {
            float p0 = __expf(sacc[nt][0] - mn0);
            float p1 = __expf(sacc[nt][1] - mn0);
            float p2 = __expf(sacc[nt][2] - mn1);
            float p3 = __expf(sacc[nt][3] - mn1);
            rs0 += p0 + p1; rs1 += p2 + p3;
            int c = nt*8 + 2*th;
            *(uint2*)&Ps[prow0 + c] = make_uint2(f2tf32(p0), f2tf32(p1));
            *(uint2*)&Ps[prow1 + c] = make_uint2(f2tf32(p2), f2tf32(p3));
        }
        rs0 += __shfl_xor_sync(0xffffffffu, rs0, 1);
        rs0 += __shfl_xor_sync(0xffffffffu, rs0, 2);
        rs1 += __shfl_xor_sync(0xffffffffu, rs1, 1);
        rs1 += __shfl_xor_sync(0xffffffffu, rs1, 2);
        l0 = l0 * a0 + rs0; l1 = l1 * a1 + rs1;
        m0r = mn0; m1r = mn1;
        #pragma unroll
        for (int nt = 0; nt < 4; nt++) {
            oacc[nt][0] *= a0; oacc[nt][1] *= a0;
            oacc[nt][2] *= a1; oacc[nt][3] *= a1;
        }
        __syncwarp();               // Ps warp-private: order stores before loads

        // ---- O += P @ V : warp computes 16x32 ----
        #pragma unroll
        for (int kk = 0; kk < 64; kk += 8) {
            uint32_t afr[4];
            afr[0] = Ps[prow0 + kk + th];
            afr[1] = Ps[prow1 + kk + th];
            afr[2] = Ps[prow0 + kk + th + 4];
            afr[3] = Ps[prow1 + kk + th + 4];
            #pragma unroll
            for (int nt = 0; nt < 4; nt++) {
                uint32_t bfr[2];
                int nc = nt * 8 + grp;
                bfr[0] = Vs[(kk + th) * LDV + nc];
                bfr[1] = Vs[(kk + th + 4) * LDV + nc];
                mma_tf32(oacc[nt], afr, bfr);
            }
        }
    }

    float inv0 = 1.f / l0, inv1 = 1.f / l1;
    int qg = q0 + warp*16 + grp;
    size_t base0 = ((size_t)(b*SqL + qg    ))*Dd + h*DHd;
    size_t base1 = ((size_t)(b*SqL + qg + 8))*Dd + h*DHd;
    #pragma unroll
    for (int nt = 0; nt < 4; nt++) {
        int c = nt*8 + 2*th;
        O[base0 + c]     = oacc[nt][0] * inv0;
        O[base0 + c + 1] = oacc[nt][1] * inv0;
        O[base1 + c]     = oacc[nt][2] * inv1;
        O[base1 + c + 1] = oacc[nt][3] * inv1;
    }
}

// ---------------- host orchestration ----------------
extern "C" void kernel_launch(void* const* d_in, const int* in_sizes, int n_in,
                              void* d_out, int out_size)
{
    const float* encoded = (const float*)d_in[0];
    const int*   seq     = (const int*)  d_in[1];
    const float* emb     = (const float*)d_in[2];
    const float* pos     = (const float*)d_in[3];
    const float* obias   = (const float*)d_in[4];
    const float* sa_qkv  = (const float*)d_in[5];
    const float* sa_o    = (const float*)d_in[6];
    const float* ca_q    = (const float*)d_in[7];
    const float* ca_kv   = (const float*)d_in[8];
    const float* ca_o    = (const float*)d_in[9];
    const float* ffn_w1  = (const float*)d_in[10];
    const float* ffn_b1  = (const float*)d_in[11];
    const float* ffn_w2  = (const float*)d_in[12];
    const float* ffn_b2  = (const float*)d_in[13];
    const float* ln_g    = (const float*)d_in[14];
    const float* ln_b    = (const float*)d_in[15];
    const float* fin_g   = (const float*)d_in[16];
    const float* fin_b   = (const float*)d_in[17];
    float* out = (float*)d_out;

    float *x, *q, *k, *v, *attn, *proj, *ffn;
    cudaGetSymbolAddress((void**)&x,    g_x);
    cudaGetSymbolAddress((void**)&q,    g_q);
    cudaGetSymbolAddress((void**)&k,    g_k);
    cudaGetSymbolAddress((void**)&v,    g_v);
    cudaGetSymbolAddress((void**)&attn, g_attn);
    cudaGetSymbolAddress((void**)&proj, g_proj);
    cudaGetSymbolAddress((void**)&ffn,  g_ffn);

    const int NQ = Bb * Ss;   // 8192
    const int NE = Bb * Mm;   // 16384

    dim3 gProj(Dd/128,  NQ/128);
    dim3 gKV  (Dd/128,  NE/128);
    dim3 gF1  (Ff/128,  NQ/128);
    dim3 gF2  (Dd/128,  NQ/128);
    dim3 gOut ((Vv + 127)/128, NQ/128);
    dim3 gAttn(Ss/64, Bb*Hh);

    embed_kernel<<<NQ, 256>>>(seq, emb, pos, x);

    for (int i = 0; i < Ll; i++) {
        const float* Wq = sa_qkv + ((size_t)i*3 + 0)*Dd*Dd;
        const float* Wk = sa_qkv + ((size_t)i*3 + 1)*Dd*Dd;
        const float* Wv = sa_qkv + ((size_t)i*3 + 2)*Dd*Dd;

        // ---- self attention ----
        gemm_tc<false,false><<<gProj, 256>>>(x, Wq, nullptr, q, NQ, Dd, Dd);
        gemm_tc<false,false><<<gProj, 256>>>(x, Wk, nullptr, k, NQ, Dd, Dd);
        gemm_tc<false,false><<<gProj, 256>>>(x, Wv, nullptr, v, NQ, Dd, Dd);
        attn_tc<<<gAttn, 128>>>(q, k, v, attn, Ss, Ss, 1);
        gemm_tc<false,false><<<gProj, 256>>>(attn, sa_o + (size_t)i*Dd*Dd,
                                             nullptr, proj, NQ, Dd, Dd);
        ln_kernel<<<NQ, 256>>>(x, proj, ln_g + ((size_t)i*3 + 0)*Dd,
                               ln_b + ((size_t)i*3 + 0)*Dd, x);

        // ---- cross attention ----
        gemm_tc<false,false><<<gProj, 256>>>(x, ca_q + (size_t)i*Dd*Dd,
                                             nullptr, q, NQ, Dd, Dd);
        gemm_tc<false,false><<<gKV, 256>>>(encoded,
                                           ca_kv + ((size_t)i*2 + 0)*Dd*Dd,
                                           nullptr, k, NE, Dd, Dd);
        gemm_tc<false,false><<<gKV, 256>>>(encoded,
                                           ca_kv + ((size_t)i*2 + 1)*Dd*Dd,
                                           nullptr, v, NE, Dd, Dd);
        attn_tc<<<gAttn, 128>>>(q, k, v, attn, Ss, Mm, 0);
        gemm_tc<false,false><<<gProj, 256>>>(attn, ca_o + (size_t)i*Dd*Dd,
                                             nullptr, proj, NQ, Dd, Dd);
        ln_kernel<<<NQ, 256>>>(x, proj, ln_g + ((size_t)i*3 + 1)*Dd,
                               ln_b + ((size_t)i*3 + 1)*Dd, x);

        // ---- FFN ----
        gemm_tc<false,true ><<<gF1, 256>>>(x, ffn_w1 + (size_t)i*Dd*Ff,
                                           ffn_b1 + (size_t)i*Ff, ffn, NQ, Ff, Dd);
        gemm_tc<false,false><<<gF2, 256>>>(ffn, ffn_w2 + (size_t)i*Ff*Dd,
                                           ffn_b2 + (size_t)i*Dd, proj, NQ, Dd, Ff);
        ln_kernel<<<NQ, 256>>>(x, proj, ln_g + ((size_t)i*3 + 2)*Dd,
                               ln_b + ((size_t)i*3 + 2)*Dd, x);
    }

    ln_kernel<<<NQ, 256>>>(x, nullptr, fin_g, fin_b, x);
    gemm_tc<true,false><<<gOut, 256>>>(x, emb, obias, out, NQ, Vv, Dd);
}

// round 10
// speedup vs baseline: 3.2103x; 1.0646x over previous
#include <cuda_runtime.h>
#include <cstdint>

#define Bb   16
#define Ss   512
#define Mm   1024
#define Dd   256
#define Hh   8
#define DHd  32
#define Ff   1024
#define Vv   3000
#define Ll   6

// ---------------- scratch (device globals; allocation-free) ----------------
__device__ float g_x   [Bb*Ss*Dd];
__device__ float g_q   [Bb*Ss*Dd];
__device__ float g_k   [Bb*Mm*Dd];
__device__ float g_v   [Bb*Mm*Dd];
__device__ float g_attn[Bb*Ss*Dd];
__device__ float g_proj[Bb*Ss*Dd];
__device__ float g_ffn [Bb*Ss*Ff];

// ---------------- embedding ----------------
__global__ void embed_kernel(const int* __restrict__ seq,
                             const float* __restrict__ emb,
                             const float* __restrict__ pos,
                             float* __restrict__ x)
{
    int row = blockIdx.x;
    int t   = threadIdx.x;
    int s   = row & (Ss - 1);
    int tok = seq[row];
    x[(size_t)row*Dd + t] = emb[(size_t)tok*Dd + t] + pos[(size_t)s*Dd + t];
}

// ---------------- add-residual + LayerNorm (warp-shuffle reduction) ----------------
__global__ void ln_kernel(const float* __restrict__ x, const float* __restrict__ r,
                          const float* __restrict__ g, const float* __restrict__ b,
                          float* __restrict__ y)
{
    __shared__ float red[8];
    int row = blockIdx.x, t = threadIdx.x;
    int warp = t >> 5, lane = t & 31;
    float v = x[(size_t)row*Dd + t];
    if (r) v += r[(size_t)row*Dd + t];

    float s = v;
    #pragma unroll
    for (int off = 16; off > 0; off >>= 1) s += __shfl_xor_sync(~0u, s, off);
    if (lane == 0) red[warp] = s;
    __syncthreads();
    float tot = 0.f;
    #pragma unroll
    for (int i = 0; i < 8; i++) tot += red[i];
    float mu = tot * (1.0f / Dd);
    __syncthreads();

    float dv = v - mu;
    s = dv * dv;
    #pragma unroll
    for (int off = 16; off > 0; off >>= 1) s += __shfl_xor_sync(~0u, s, off);
    if (lane == 0) red[warp] = s;
    __syncthreads();
    tot = 0.f;
    #pragma unroll
    for (int i = 0; i < 8; i++) tot += red[i];
    float var = tot * (1.0f / Dd);

    y[(size_t)row*Dd + t] = dv * rsqrtf(var + 1e-5f) * g[t] + b[t];
}

// ---------------- tf32 helpers ----------------
__device__ __forceinline__ uint32_t f2tf32(float x) {
    uint32_t y; asm("cvt.rna.tf32.f32 %0, %1;" : "=r"(y) : "f"(x)); return y;
}

__device__ __forceinline__ void mma_tf32(float* d, const uint32_t* a, const uint32_t* b) {
    asm volatile(
        "mma.sync.aligned.m16n8k8.row.col.f32.tf32.tf32.f32 "
        "{%0,%1,%2,%3}, {%4,%5,%6,%7}, {%8,%9}, {%0,%1,%2,%3};"
        : "+f"(d[0]), "+f"(d[1]), "+f"(d[2]), "+f"(d[3])
        : "r"(a[0]), "r"(a[1]), "r"(a[2]), "r"(a[3]), "r"(b[0]), "r"(b[1]));
}

// ---------------- tf32 tensor-core GEMM ----------------
// C = A @ B (+bias)(+relu).  A [M,K] row-major.
// TRANSB=false: B [K,N]; TRANSB=true: B [N,K] (C = A @ B^T).
// BM x 128 C tile, K-tile 32, 256 threads.
//   BM=128: 8 warps 2x4, warp tile 64x32 (NT=4)
//   BM=64 : 8 warps 1x8, warp tile 64x16 (NT=2) -- doubles grid for small-N GEMMs
// Multi-output: blockIdx.z selects weight slice Bw + z*bstride and output C{z}.
// M % BM == 0, K % 32 == 0 required (true at all call sites); N bounds-checked.
#define LDA 36      // 32 + 4 : A/NT-B fragment-read bank = 4*grp+th (conflict-free)
#define LDB 136     // 128 + 8: NN-B fragment-read bank = 8*th+grp (conflict-free)

template<int BM, bool TRANSB, bool RELU>
__global__ void __launch_bounds__(256)
gemm_tc(const float* __restrict__ A, const float* __restrict__ Bw, size_t bstride,
        const float* __restrict__ bias, float* __restrict__ C0,
        float* __restrict__ C1, float* __restrict__ C2,
        int M, int N, int K)
{
    constexpr int NT = (BM == 128) ? 4 : 2;      // 8-col n-tiles per warp
    __shared__ uint32_t As[BM * LDA];
    __shared__ uint32_t Bs[128 * LDA];           // NT: [128][36]; NN: [32][136] (4352<4608)

    int z = blockIdx.z;
    const float* Bm = Bw + (size_t)z * bstride;
    float* C = (z == 0) ? C0 : ((z == 1) ? C1 : C2);

    int tid  = threadIdx.x;
    int warp = tid >> 5, lane = tid & 31;
    int wm = (BM == 128) ? (warp >> 2) : 0;
    int wn = (BM == 128) ? (warp & 3) : warp;
    int grp = lane >> 2, th = lane & 3;
    int m0 = blockIdx.y * BM, n0 = blockIdx.x * 128;

    float acc[4][NT][4] = {};

    for (int k0 = 0; k0 < K; k0 += 32) {
        // ---- A tile: BM x 32, float4, convert to tf32 at store ----
        #pragma unroll
        for (int i = 0; i < BM/32; i++) {
            int e = tid + i * 256;
            int r = e >> 3, c = (e & 7) * 4;
            float4 v = *(const float4*)&A[(size_t)(m0 + r) * K + k0 + c];
            uint32_t* p = &As[r * LDA + c];
            p[0] = f2tf32(v.x); p[1] = f2tf32(v.y); p[2] = f2tf32(v.z); p[3] = f2tf32(v.w);
        }
        if (TRANSB) {
            #pragma unroll
            for (int i = 0; i < 4; i++) {
                int e = tid + i * 256;
                int r = e >> 3, c = (e & 7) * 4;
                int n = n0 + r;
                float4 v = (n < N) ? *(const float4*)&Bm[(size_t)n * K + k0 + c]
                                   : make_float4(0.f, 0.f, 0.f, 0.f);
                uint32_t* p = &Bs[r * LDA + c];
                p[0] = f2tf32(v.x); p[1] = f2tf32(v.y); p[2] = f2tf32(v.z); p[3] = f2tf32(v.w);
            }
        } else {
            #pragma unroll
            for (int i = 0; i < 4; i++) {
                int e = tid + i * 256;
                int r = e >> 5, c = (e & 31) * 4;
                float4 v = *(const float4*)&Bm[(size_t)(k0 + r) * N + n0 + c];
                uint32_t* p = &Bs[r * LDB + c];
                p[0] = f2tf32(v.x); p[1] = f2tf32(v.y); p[2] = f2tf32(v.z); p[3] = f2tf32(v.w);
            }
        }
        __syncthreads();

        #pragma unroll
        for (int kk = 0; kk < 32; kk += 8) {
            uint32_t afr[4][4], bfr[NT][2];
            #pragma unroll
            for (int mt = 0; mt < 4; mt++) {
                int mr = (wm * 64 + mt * 16) * LDA + kk;
                afr[mt][0] = As[mr + grp * LDA + th];
                afr[mt][1] = As[mr + (grp + 8) * LDA + th];
                afr[mt][2] = As[mr + grp * LDA + th + 4];
                afr[mt][3] = As[mr + (grp + 8) * LDA + th + 4];
            }
            #pragma unroll
            for (int nt = 0; nt < NT; nt++) {
                int nc = wn * (8 * NT) + nt * 8 + grp;
                if (TRANSB) {
                    bfr[nt][0] = Bs[nc * LDA + kk + th];
                    bfr[nt][1] = Bs[nc * LDA + kk + th + 4];
                } else {
                    bfr[nt][0] = Bs[(kk + th) * LDB + nc];
                    bfr[nt][1] = Bs[(kk + th + 4) * LDB + nc];
                }
            }
            #pragma unroll
            for (int mt = 0; mt < 4; mt++)
                #pragma unroll
                for (int nt = 0; nt < NT; nt++)
                    mma_tf32(acc[mt][nt], afr[mt], bfr[nt]);
        }
        __syncthreads();
    }

    #pragma unroll
    for (int mt = 0; mt < 4; mt++) {
        int row0 = m0 + wm * 64 + mt * 16 + grp;
        #pragma unroll
        for (int nt = 0; nt < NT; nt++) {
            int col = n0 + wn * (8 * NT) + nt * 8 + th * 2;
            float bi0 = bias ? bias[min(col, N - 1)] : 0.f;
            float bi1 = bias ? bias[min(col + 1, N - 1)] : 0.f;
            #pragma unroll
            for (int half = 0; half < 2; half++) {
                int row = row0 + half * 8;
                float v0 = acc[mt][nt][half * 2 + 0] + bi0;
                float v1 = acc[mt][nt][half * 2 + 1] + bi1;
                if (RELU) { v0 = fmaxf(v0, 0.f); v1 = fmaxf(v1, 0.f); }
                if (col < N)     C[(size_t)row * N + col]     = v0;
                if (col + 1 < N) C[(size_t)row * N + col + 1] = v1;
            }
        }
    }
}

// ---------------- tf32 tensor-core flash attention (DH=32) ----------------
#define LDQ 36
#define LDV 40
#define LDP 68

__global__ void __launch_bounds__(128)
attn_tc(const float* __restrict__ Q, const float* __restrict__ K,
        const float* __restrict__ V, float* __restrict__ O,
        int SqL, int SkvL, int causal)
{
    __shared__ uint32_t Qs[64 * LDQ];
    __shared__ uint32_t Ks[64 * LDQ];
    __shared__ uint32_t Vs[64 * LDV];
    __shared__ uint32_t Ps[64 * LDP];
    int tid = threadIdx.x;
    int warp = tid >> 5, lane = tid & 31;
    int grp = lane >> 2, th = lane & 3;
    int b = blockIdx.y >> 3, h = blockIdx.y & 7;
    int q0 = blockIdx.x * 64;
    const float scale = 0.17677669529663687f;   // 1/sqrt(32)

    #pragma unroll
    for (int i = 0; i < 4; i++) {
        int e = tid + i * 128;
        int r = e >> 3, c = (e & 7) * 4;
        float4 v = *(const float4*)&Q[((size_t)(b*SqL + q0 + r))*Dd + h*DHd + c];
        uint32_t* p = &Qs[r * LDQ + c];
        p[0] = f2tf32(v.x*scale); p[1] = f2tf32(v.y*scale);
        p[2] = f2tf32(v.z*scale); p[3] = f2tf32(v.w*scale);
    }

    float m0r = -1e30f, m1r = -1e30f, l0 = 0.f, l1 = 0.f;
    float oacc[4][4] = {};
    int prow0 = (warp*16 + grp) * LDP;
    int prow1 = (warp*16 + grp + 8) * LDP;

    int nkt = causal ? ((int)blockIdx.x + 1) : (SkvL >> 6);
    for (int kt = 0; kt < nkt; kt++) {
        int k0 = kt * 64;
        __syncthreads();
        #pragma unroll
        for (int i = 0; i < 4; i++) {
            int e = tid + i * 128;
            int r = e >> 3, c = (e & 7) * 4;
            size_t gi = ((size_t)(b*SkvL + k0 + r))*Dd + h*DHd + c;
            float4 kv = *(const float4*)&K[gi];
            float4 vv = *(const float4*)&V[gi];
            uint32_t* pk = &Ks[r * LDQ + c];
            pk[0] = f2tf32(kv.x); pk[1] = f2tf32(kv.y); pk[2] = f2tf32(kv.z); pk[3] = f2tf32(kv.w);
            uint32_t* pv = &Vs[r * LDV + c];
            pv[0] = f2tf32(vv.x); pv[1] = f2tf32(vv.y); pv[2] = f2tf32(vv.z); pv[3] = f2tf32(vv.w);
        }
        __syncthreads();

        float sacc[8][4] = {};
        #pragma unroll
        for (int kk = 0; kk < 32; kk += 8) {
            uint32_t afr[4];
            int mr = (warp*16) * LDQ + kk;
            afr[0] = Qs[mr + grp * LDQ + th];
            afr[1] = Qs[mr + (grp + 8) * LDQ + th];
            afr[2] = Qs[mr + grp * LDQ + th + 4];
            afr[3] = Qs[mr + (grp + 8) * LDQ + th + 4];
            #pragma unroll
            for (int nt = 0; nt < 8; nt++) {
                uint32_t bfr[2];
                int nc = nt * 8 + grp;
                bfr[0] = Ks[nc * LDQ + kk + th];
                bfr[1] = Ks[nc * LDQ + kk + th + 4];
                mma_tf32(sacc[nt], afr, bfr);
            }
        }

        if (causal && kt == (int)blockIdx.x) {
            int qg = q0 + warp*16 + grp;
            #pragma unroll
            for (int nt = 0; nt < 8; nt++) {
                int kv0 = k0 + nt*8 + 2*th;
                if (kv0     > qg)     sacc[nt][0] = -1e9f;
                if (kv0 + 1 > qg)     sacc[nt][1] = -1e9f;
                if (kv0     > qg + 8) sacc[nt][2] = -1e9f;
                if (kv0 + 1 > qg + 8) sacc[nt][3] = -1e9f;
            }
        }

        float rm0 = -1e30f, rm1 = -1e30f;
        #pragma unroll
        for (int nt = 0; nt < 8; nt++) {
            rm0 = fmaxf(rm0, fmaxf(sacc[nt][0], sacc[nt][1]));
            rm1 = fmaxf(rm1, fmaxf(sacc[nt][2], sacc[nt][3]));
        }
        rm0 = fmaxf(rm0, __shfl_xor_sync(0xffffffffu, rm0, 1));
        rm0 = fmaxf(rm0, __shfl_xor_sync(0xffffffffu, rm0, 2));
        rm1 = fmaxf(rm1, __shfl_xor_sync(0xffffffffu, rm1, 1));
        rm1 = fmaxf(rm1, __shfl_xor_sync(0xffffffffu, rm1, 2));
        float mn0 = fmaxf(m0r, rm0), mn1 = fmaxf(m1r, rm1);
        float a0 = __expf(m0r - mn0), a1 = __expf(m1r - mn1);
        float rs0 = 0.f, rs1 = 0.f;
        #pragma unroll
        for (int nt = 0; nt < 8; nt++) {
            float p0 = __expf(sacc[nt][0] - mn0);
            float p1 = __expf(sacc[nt][1] - mn0);
            float p2 = __expf(sacc[nt][2] - mn1);
            float p3 = __expf(sacc[nt][3] - mn1);
            rs0 += p0 + p1; rs1 += p2 + p3;
            int c = nt*8 + 2*th;
            *(uint2*)&Ps[prow0 + c] = make_uint2(f2tf32(p0), f2tf32(p1));
            *(uint2*)&Ps[prow1 + c] = make_uint2(f2tf32(p2), f2tf32(p3));
        }
        rs0 += __shfl_xor_sync(0xffffffffu, rs0, 1);
        rs0 += __shfl_xor_sync(0xffffffffu, rs0, 2);
        rs1 += __shfl_xor_sync(0xffffffffu, rs1, 1);
        rs1 += __shfl_xor_sync(0xffffffffu, rs1, 2);
        l0 = l0 * a0 + rs0; l1 = l1 * a1 + rs1;
        m0r = mn0; m1r = mn1;
        #pragma unroll
        for (int nt = 0; nt < 4; nt++) {
            oacc[nt][0] *= a0; oacc[nt][1] *= a0;
            oacc[nt][2] *= a1; oacc[nt][3] *= a1;
        }
        __syncwarp();

        #pragma unroll
        for (int kk = 0; kk < 64; kk += 8) {
            uint32_t afr[4];
            afr[0] = Ps[prow0 + kk + th];
            afr[1] = Ps[prow1 + kk + th];
            afr[2] = Ps[prow0 + kk + th + 4];
            afr[3] = Ps[prow1 + kk + th + 4];
            #pragma unroll
            for (int nt = 0; nt < 4; nt++) {
                uint32_t bfr[2];
                int nc = nt * 8 + grp;
                bfr[0] = Vs[(kk + th) * LDV + nc];
                bfr[1] = Vs[(kk + th + 4) * LDV + nc];
                mma_tf32(oacc[nt], afr, bfr);
            }
        }
    }

    float inv0 = 1.f / l0, inv1 = 1.f / l1;
    int qg = q0 + warp*16 + grp;
    size_t base0 = ((size_t)(b*SqL + qg    ))*Dd + h*DHd;
    size_t base1 = ((size_t)(b*SqL + qg + 8))*Dd + h*DHd;
    #pragma unroll
    for (int nt = 0; nt < 4; nt++) {
        int c = nt*8 + 2*th;
        O[base0 + c]     = oacc[nt][0] * inv0;
        O[base0 + c + 1] = oacc[nt][1] * inv0;
        O[base1 + c]     = oacc[nt][2] * inv1;
        O[base1 + c + 1] = oacc[nt][3] * inv1;
    }
}

// ---------------- host orchestration ----------------
extern "C" void kernel_launch(void* const* d_in, const int* in_sizes, int n_in,
                              void* d_out, int out_size)
{
    const float* encoded = (const float*)d_in[0];
    const int*   seq     = (const int*)  d_in[1];
    const float* emb     = (const float*)d_in[2];
    const float* pos     = (const float*)d_in[3];
    const float* obias   = (const float*)d_in[4];
    const float* sa_qkv  = (const float*)d_in[5];
    const float* sa_o    = (const float*)d_in[6];
    const float* ca_q    = (const float*)d_in[7];
    const float* ca_kv   = (const float*)d_in[8];
    const float* ca_o    = (const float*)d_in[9];
    const float* ffn_w1  = (const float*)d_in[10];
    const float* ffn_b1  = (const float*)d_in[11];
    const float* ffn_w2  = (const float*)d_in[12];
    const float* ffn_b2  = (const float*)d_in[13];
    const float* ln_g    = (const float*)d_in[14];
    const float* ln_b    = (const float*)d_in[15];
    const float* fin_g   = (const float*)d_in[16];
    const float* fin_b   = (const float*)d_in[17];
    float* out = (float*)d_out;

    float *x, *q, *k, *v, *attn, *proj, *ffn;
    cudaGetSymbolAddress((void**)&x,    g_x);
    cudaGetSymbolAddress((void**)&q,    g_q);
    cudaGetSymbolAddress((void**)&k,    g_k);
    cudaGetSymbolAddress((void**)&v,    g_v);
    cudaGetSymbolAddress((void**)&attn, g_attn);
    cudaGetSymbolAddress((void**)&proj, g_proj);
    cudaGetSymbolAddress((void**)&ffn,  g_ffn);

    const int NQ = Bb * Ss;   // 8192
    const int NE = Bb * Mm;   // 16384
    const size_t DD = (size_t)Dd * Dd;

    dim3 gQKV (Dd/128, NQ/64, 3);         // fused q/k/v projections (768 CTAs)
    dim3 gProj(Dd/128, NQ/64, 1);         // single small-N gemm (256 CTAs)
    dim3 gCKV (Dd/128, NE/64, 2);         // fused cross k/v (1024 CTAs)
    dim3 gF1  (Ff/128, NQ/128, 1);        // ffn up (512 CTAs)
    dim3 gF2  (Dd/128, NQ/64, 1);         // ffn down (256 CTAs)
    dim3 gOut ((Vv + 127)/128, NQ/128, 1);// logits (1536 CTAs)
    dim3 gAttn(Ss/64, Bb*Hh);

    embed_kernel<<<NQ, 256>>>(seq, emb, pos, x);

    for (int i = 0; i < Ll; i++) {
        // ---- self attention ----
        gemm_tc<64,false,false><<<gQKV, 256>>>(x, sa_qkv + (size_t)i*3*DD, DD,
                                               nullptr, q, k, v, NQ, Dd, Dd);
        attn_tc<<<gAttn, 128>>>(q, k, v, attn, Ss, Ss, 1);
        gemm_tc<64,false,false><<<gProj, 256>>>(attn, sa_o + (size_t)i*DD, 0,
                                                nullptr, proj, nullptr, nullptr,
                                                NQ, Dd, Dd);
        ln_kernel<<<NQ, 256>>>(x, proj, ln_g + ((size_t)i*3 + 0)*Dd,
                               ln_b + ((size_t)i*3 + 0)*Dd, x);

        // ---- cross attention ----
        gemm_tc<64,false,false><<<gProj, 256>>>(x, ca_q + (size_t)i*DD, 0,
                                                nullptr, q, nullptr, nullptr,
                                                NQ, Dd, Dd);
        gemm_tc<64,false,false><<<gCKV, 256>>>(encoded, ca_kv + (size_t)i*2*DD, DD,
                                               nullptr, k, v, nullptr, NE, Dd, Dd);
        attn_tc<<<gAttn, 128>>>(q, k, v, attn, Ss, Mm, 0);
        gemm_tc<64,false,false><<<gProj, 256>>>(attn, ca_o + (size_t)i*DD, 0,
                                                nullptr, proj, nullptr, nullptr,
                                                NQ, Dd, Dd);
        ln_kernel<<<NQ, 256>>>(x, proj, ln_g + ((size_t)i*3 + 1)*Dd,
                               ln_b + ((size_t)i*3 + 1)*Dd, x);

        // ---- FFN ----
        gemm_tc<128,false,true ><<<gF1, 256>>>(x, ffn_w1 + (size_t)i*Dd*Ff, 0,
                                               ffn_b1 + (size_t)i*Ff, ffn,
                                               nullptr, nullptr, NQ, Ff, Dd);
        gemm_tc<64,false,false><<<gF2, 256>>>(ffn, ffn_w2 + (size_t)i*Ff*Dd, 0,
                                              ffn_b2 + (size_t)i*Dd, proj,
                                              nullptr, nullptr, NQ, Dd, Ff);
        ln_kernel<<<NQ, 256>>>(x, proj, ln_g + ((size_t)i*3 + 2)*Dd,
                               ln_b + ((size_t)i*3 + 2)*Dd, x);
    }

    ln_kernel<<<NQ, 256>>>(x, nullptr, fin_g, fin_b, x);
    gemm_tc<128,true,false><<<gOut, 256>>>(x, emb, 0, obias, out,
                                           nullptr, nullptr, NQ, Vv, Dd);
}

// round 13
// speedup vs baseline: 3.3904x; 1.0561x over previous
#include <cuda_runtime.h>
#include <cstdint>

#define Bb   16
#define Ss   512
#define Mm   1024
#define Dd   256
#define Hh   8
#define DHd  32
#define Ff   1024
#define Vv   3000
#define Ll   6

// ---------------- scratch (device globals; allocation-free) ----------------
__device__ float g_x   [Bb*Ss*Dd];
__device__ float g_q   [Bb*Ss*Dd];
__device__ float g_k   [Bb*Mm*Dd];
__device__ float g_v   [Bb*Mm*Dd];
__device__ float g_attn[Bb*Ss*Dd];
__device__ float g_proj[Bb*Ss*Dd];
__device__ float g_ffn [Bb*Ss*Ff];

// ---------------- embedding ----------------
__global__ void embed_kernel(const int* __restrict__ seq,
                             const float* __restrict__ emb,
                             const float* __restrict__ pos,
                             float* __restrict__ x)
{
    int row = blockIdx.x;
    int t   = threadIdx.x;
    int s   = row & (Ss - 1);
    int tok = seq[row];
    x[(size_t)row*Dd + t] = emb[(size_t)tok*Dd + t] + pos[(size_t)s*Dd + t];
}

// ---------------- add-residual + LayerNorm (warp-shuffle reduction) ----------------
__global__ void ln_kernel(const float* __restrict__ x, const float* __restrict__ r,
                          const float* __restrict__ g, const float* __restrict__ b,
                          float* __restrict__ y)
{
    __shared__ float red[8];
    int row = blockIdx.x, t = threadIdx.x;
    int warp = t >> 5, lane = t & 31;
    float v = x[(size_t)row*Dd + t];
    if (r) v += r[(size_t)row*Dd + t];

    float s = v;
    #pragma unroll
    for (int off = 16; off > 0; off >>= 1) s += __shfl_xor_sync(~0u, s, off);
    if (lane == 0) red[warp] = s;
    __syncthreads();
    float tot = 0.f;
    #pragma unroll
    for (int i = 0; i < 8; i++) tot += red[i];
    float mu = tot * (1.0f / Dd);
    __syncthreads();

    float dv = v - mu;
    s = dv * dv;
    #pragma unroll
    for (int off = 16; off > 0; off >>= 1) s += __shfl_xor_sync(~0u, s, off);
    if (lane == 0) red[warp] = s;
    __syncthreads();
    tot = 0.f;
    #pragma unroll
    for (int i = 0; i < 8; i++) tot += red[i];
    float var = tot * (1.0f / Dd);

    y[(size_t)row*Dd + t] = dv * rsqrtf(var + 1e-5f) * g[t] + b[t];
}

// ---------------- tf32 helpers ----------------
__device__ __forceinline__ uint32_t f2tf32(float x) {
    uint32_t y; asm("cvt.rna.tf32.f32 %0, %1;" : "=r"(y) : "f"(x)); return y;
}

__device__ __forceinline__ void mma_tf32(float* d, const uint32_t* a, const uint32_t* b) {
    asm volatile(
        "mma.sync.aligned.m16n8k8.row.col.f32.tf32.tf32.f32 "
        "{%0,%1,%2,%3}, {%4,%5,%6,%7}, {%8,%9}, {%0,%1,%2,%3};"
        : "+f"(d[0]), "+f"(d[1]), "+f"(d[2]), "+f"(d[3])
        : "r"(a[0]), "r"(a[1]), "r"(a[2]), "r"(a[3]), "r"(b[0]), "r"(b[1]));
}

// ---------------- tf32 tensor-core GEMM (register double-buffered) ----------------
// C = A @ B (+bias)(+relu).  A [M,K] row-major.
// TRANSB=false: B [K,N]; TRANSB=true: B [N,K] (C = A @ B^T).
// BM x 128 C tile, K-tile 32, 256 threads.
// Next k-tile's global loads are issued into registers right after the post-store
// barrier, hiding LDG/L2 latency behind the mma loop of the current tile.
#define LDA 36      // 32 + 4 : A/NT-B fragment-read bank = 4*grp+th (conflict-free)
#define LDB 136     // 128 + 8: NN-B fragment-read bank = 8*th+grp (conflict-free)

template<int BM, bool TRANSB, bool RELU>
__global__ void __launch_bounds__(256)
gemm_tc(const float* __restrict__ A, const float* __restrict__ Bw, size_t bstride,
        const float* __restrict__ bias, float* __restrict__ C0,
        float* __restrict__ C1, float* __restrict__ C2,
        int M, int N, int K)
{
    constexpr int NT   = (BM == 128) ? 4 : 2;     // 8-col n-tiles per warp
    constexpr int AREG = BM / 32;                 // float4 per thread for A tile
    __shared__ uint32_t As[BM * LDA];
    __shared__ uint32_t Bs[128 * LDA];            // NT: [128][36]; NN: [32][136]

    int z = blockIdx.z;
    const float* Bm = Bw + (size_t)z * bstride;
    float* C = (z == 0) ? C0 : ((z == 1) ? C1 : C2);

    int tid  = threadIdx.x;
    int warp = tid >> 5, lane = tid & 31;
    int wm = (BM == 128) ? (warp >> 2) : 0;
    int wn = (BM == 128) ? (warp & 3) : warp;
    int grp = lane >> 2, th = lane & 3;
    int m0 = blockIdx.y * BM, n0 = blockIdx.x * 128;

    float4 ra[AREG], rb[4];

    auto load_tile = [&](int k0) {
        #pragma unroll
        for (int i = 0; i < AREG; i++) {
            int e = tid + i * 256;
            int r = e >> 3, c = (e & 7) * 4;
            ra[i] = *(const float4*)&A[(size_t)(m0 + r) * K + k0 + c];
        }
        if (TRANSB) {
            #pragma unroll
            for (int i = 0; i < 4; i++) {
                int e = tid + i * 256;
                int r = e >> 3, c = (e & 7) * 4;
                int n = n0 + r;
                rb[i] = (n < N) ? *(const float4*)&Bm[(size_t)n * K + k0 + c]
                                : make_float4(0.f, 0.f, 0.f, 0.f);
            }
        } else {
            #pragma unroll
            for (int i = 0; i < 4; i++) {
                int e = tid + i * 256;
                int r = e >> 5, c = (e & 31) * 4;
                rb[i] = *(const float4*)&Bm[(size_t)(k0 + r) * N + n0 + c];
            }
        }
    };

    auto store_tile = [&]() {
        #pragma unroll
        for (int i = 0; i < AREG; i++) {
            int e = tid + i * 256;
            int r = e >> 3, c = (e & 7) * 4;
            uint32_t* p = &As[r * LDA + c];
            p[0] = f2tf32(ra[i].x); p[1] = f2tf32(ra[i].y);
            p[2] = f2tf32(ra[i].z); p[3] = f2tf32(ra[i].w);
        }
        #pragma unroll
        for (int i = 0; i < 4; i++) {
            int e = tid + i * 256;
            uint32_t* p;
            if (TRANSB) { int r = e >> 3, c = (e & 7) * 4;  p = &Bs[r * LDA + c]; }
            else        { int r = e >> 5, c = (e & 31) * 4; p = &Bs[r * LDB + c]; }
            p[0] = f2tf32(rb[i].x); p[1] = f2tf32(rb[i].y);
            p[2] = f2tf32(rb[i].z); p[3] = f2tf32(rb[i].w);
        }
    };

    float acc[4][NT][4] = {};

    load_tile(0);
    for (int k0 = 0; k0 < K; k0 += 32) {
        store_tile();
        __syncthreads();
        if (k0 + 32 < K) load_tile(k0 + 32);   // in flight during mma loop

        #pragma unroll
        for (int kk = 0; kk < 32; kk += 8) {
            uint32_t afr[4][4], bfr[NT][2];
            #pragma unroll
            for (int mt = 0; mt < 4; mt++) {
                int mr = (wm * 64 + mt * 16) * LDA + kk;
                afr[mt][0] = As[mr + grp * LDA + th];
                afr[mt][1] = As[mr + (grp + 8) * LDA + th];
                afr[mt][2] = As[mr + grp * LDA + th + 4];
                afr[mt][3] = As[mr + (grp + 8) * LDA + th + 4];
            }
            #pragma unroll
            for (int nt = 0; nt < NT; nt++) {
                int nc = wn * (8 * NT) + nt * 8 + grp;
                if (TRANSB) {
                    bfr[nt][0] = Bs[nc * LDA + kk + th];
                    bfr[nt][1] = Bs[nc * LDA + kk + th + 4];
                } else {
                    bfr[nt][0] = Bs[(kk + th) * LDB + nc];
                    bfr[nt][1] = Bs[(kk + th + 4) * LDB + nc];
                }
            }
            #pragma unroll
            for (int mt = 0; mt < 4; mt++)
                #pragma unroll
                for (int nt = 0; nt < NT; nt++)
                    mma_tf32(acc[mt][nt], afr[mt], bfr[nt]);
        }
        __syncthreads();
    }

    #pragma unroll
    for (int mt = 0; mt < 4; mt++) {
        int row0 = m0 + wm * 64 + mt * 16 + grp;
        #pragma unroll
        for (int nt = 0; nt < NT; nt++) {
            int col = n0 + wn * (8 * NT) + nt * 8 + th * 2;
            float bi0 = bias ? bias[min(col, N - 1)] : 0.f;
            float bi1 = bias ? bias[min(col + 1, N - 1)] : 0.f;
            #pragma unroll
            for (int half = 0; half < 2; half++) {
                int row = row0 + half * 8;
                float v0 = acc[mt][nt][half * 2 + 0] + bi0;
                float v1 = acc[mt][nt][half * 2 + 1] + bi1;
                if (RELU) { v0 = fmaxf(v0, 0.f); v1 = fmaxf(v1, 0.f); }
                if (col < N)     C[(size_t)row * N + col]     = v0;
                if (col + 1 < N) C[(size_t)row * N + col + 1] = v1;
            }
        }
    }
}

// ---------------- tf32 flash attention (register double-buffered K/V) ----------------
#define LDQ 36
#define LDV 40
#define LDP 68

__global__ void __launch_bounds__(128)
attn_tc(const float* __restrict__ Q, const float* __restrict__ K,
        const float* __restrict__ V, float* __restrict__ O,
        int SqL, int SkvL, int causal)
{
    __shared__ uint32_t Qs[64 * LDQ];
    __shared__ uint32_t Ks[64 * LDQ];
    __shared__ uint32_t Vs[64 * LDV];
    __shared__ uint32_t Ps[64 * LDP];
    int tid = threadIdx.x;
    int warp = tid >> 5, lane = tid & 31;
    int grp = lane >> 2, th = lane & 3;
    int b = blockIdx.y >> 3, h = blockIdx.y & 7;
    int q0 = blockIdx.x * 64;
    const float scale = 0.17677669529663687f;   // 1/sqrt(32)

    #pragma unroll
    for (int i = 0; i < 4; i++) {
        int e = tid + i * 128;
        int r = e >> 3, c = (e & 7) * 4;
        float4 v = *(const float4*)&Q[((size_t)(b*SqL + q0 + r))*Dd + h*DHd + c];
        uint32_t* p = &Qs[r * LDQ + c];
        p[0] = f2tf32(v.x*scale); p[1] = f2tf32(v.y*scale);
        p[2] = f2tf32(v.z*scale); p[3] = f2tf32(v.w*scale);
    }

    float4 rk[4], rv[4];
    auto load_kv = [&](int kt) {
        int k0 = kt * 64;
        #pragma unroll
        for (int i = 0; i < 4; i++) {
            int e = tid + i * 128;
            int r = e >> 3, c = (e & 7) * 4;
            size_t gi = ((size_t)(b*SkvL + k0 + r))*Dd + h*DHd + c;
            rk[i] = *(const float4*)&K[gi];
            rv[i] = *(const float4*)&V[gi];
        }
    };

    float m0r = -1e30f, m1r = -1e30f, l0 = 0.f, l1 = 0.f;
    float oacc[4][4] = {};
    int prow0 = (warp*16 + grp) * LDP;
    int prow1 = (warp*16 + grp + 8) * LDP;

    int nkt = causal ? ((int)blockIdx.x + 1) : (SkvL >> 6);
    load_kv(0);
    for (int kt = 0; kt < nkt; kt++) {
        int k0 = kt * 64;
        __syncthreads();            // previous iter's Ks/Vs/Ps consumers done
        #pragma unroll
        for (int i = 0; i < 4; i++) {
            int e = tid + i * 128;
            int r = e >> 3, c = (e & 7) * 4;
            uint32_t* pk = &Ks[r * LDQ + c];
            pk[0] = f2tf32(rk[i].x); pk[1] = f2tf32(rk[i].y);
            pk[2] = f2tf32(rk[i].z); pk[3] = f2tf32(rk[i].w);
            uint32_t* pv = &Vs[r * LDV + c];
            pv[0] = f2tf32(rv[i].x); pv[1] = f2tf32(rv[i].y);
            pv[2] = f2tf32(rv[i].z); pv[3] = f2tf32(rv[i].w);
        }
        __syncthreads();
        if (kt + 1 < nkt) load_kv(kt + 1);   // in flight during S/softmax/PV

        // ---- S = Qs @ Ks^T : warp computes 16x64 ----
        float sacc[8][4] = {};
        #pragma unroll
        for (int kk = 0; kk < 32; kk += 8) {
            uint32_t afr[4];
            int mr = (warp*16) * LDQ + kk;
            afr[0] = Qs[mr + grp * LDQ + th];
            afr[1] = Qs[mr + (grp + 8) * LDQ + th];
            afr[2] = Qs[mr + grp * LDQ + th + 4];
            afr[3] = Qs[mr + (grp + 8) * LDQ + th + 4];
            #pragma unroll
            for (int nt = 0; nt < 8; nt++) {
                uint32_t bfr[2];
                int nc = nt * 8 + grp;
                bfr[0] = Ks[nc * LDQ + kk + th];
                bfr[1] = Ks[nc * LDQ + kk + th + 4];
                mma_tf32(sacc[nt], afr, bfr);
            }
        }

        if (causal && kt == (int)blockIdx.x) {
            int qg = q0 + warp*16 + grp;
            #pragma unroll
            for (int nt = 0; nt < 8; nt++) {
                int kv0 = k0 + nt*8 + 2*th;
                if (kv0     > qg)     sacc[nt][0] = -1e9f;
                if (kv0 + 1 > qg)     sacc[nt][1] = -1e9f;
                if (kv0     > qg + 8) sacc[nt][2] = -1e9f;
                if (kv0 + 1 > qg + 8) sacc[nt][3] = -1e9f;
            }
        }

        float rm0 = -1e30f, rm1 = -1e30f;
        #pragma unroll
        for (int nt = 0; nt < 8; nt++) {
            rm0 = fmaxf(rm0, fmaxf(sacc[nt][0], sacc[nt][1]));
            rm1 = fmaxf(rm1, fmaxf(sacc[nt][2], sacc[nt][3]));
        }
        rm0 = fmaxf(rm0, __shfl_xor_sync(0xffffffffu, rm0, 1));
        rm0 = fmaxf(rm0, __shfl_xor_sync(0xffffffffu, rm0, 2));
        rm1 = fmaxf(rm1, __shfl_xor_sync(0xffffffffu, rm1, 1));
        rm1 = fmaxf(rm1, __shfl_xor_sync(0xffffffffu, rm1, 2));
        float mn0 = fmaxf(m0r, rm0), mn1 = fmaxf(m1r, rm1);
        float a0 = __expf(m0r - mn0), a1 = __expf(m1r - mn1);
        float rs0 = 0.f, rs1 = 0.f;
        #pragma unroll
        for (int nt = 0; nt < 8; nt++) {
            float p0 = __expf(sacc[nt][0] - mn0);
            float p1 = __expf(sacc[nt][1] - mn0);
            float p2 = __expf(sacc[nt][2] - mn1);
            float p3 = __expf(sacc[nt][3] - mn1);
            rs0 += p0 + p1; rs1 += p2 + p3;
            int c = nt*8 + 2*th;
            *(uint2*)&Ps[prow0 + c] = make_uint2(f2tf32(p0), f2tf32(p1));
            *(uint2*)&Ps[prow1 + c] = make_uint2(f2tf32(p2), f2tf32(p3));
        }
        rs0 += __shfl_xor_sync(0xffffffffu, rs0, 1);
        rs0 += __shfl_xor_sync(0xffffffffu, rs0, 2);
        rs1 += __shfl_xor_sync(0xffffffffu, rs1, 1);
        rs1 += __shfl_xor_sync(0xffffffffu, rs1, 2);
        l0 = l0 * a0 + rs0; l1 = l1 * a1 + rs1;
        m0r = mn0; m1r = mn1;
        #pragma unroll
        for (int nt = 0; nt < 4; nt++) {
            oacc[nt][0] *= a0; oacc[nt][1] *= a0;
            oacc[nt][2] *= a1; oacc[nt][3] *= a1;
        }
        __syncwarp();               // Ps warp-private: order stores before loads

        #pragma unroll
        for (int kk = 0; kk < 64; kk += 8) {
            uint32_t afr[4];
            afr[0] = Ps[prow0 + kk + th];
            afr[1] = Ps[prow1 + kk + th];
            afr[2] = Ps[prow0 + kk + th + 4];
            afr[3] = Ps[prow1 + kk + th + 4];
            #pragma unroll
            for (int nt = 0; nt < 4; nt++) {
                uint32_t bfr[2];
                int nc = nt * 8 + grp;
                bfr[0] = Vs[(kk + th) * LDV + nc];
                bfr[1] = Vs[(kk + th + 4) * LDV + nc];
                mma_tf32(oacc[nt], afr, bfr);
            }
        }
    }

    float inv0 = 1.f / l0, inv1 = 1.f / l1;
    int qg = q0 + warp*16 + grp;
    size_t base0 = ((size_t)(b*SqL + qg    ))*Dd + h*DHd;
    size_t base1 = ((size_t)(b*SqL + qg + 8))*Dd + h*DHd;
    #pragma unroll
    for (int nt = 0; nt < 4; nt++) {
        int c = nt*8 + 2*th;
        O[base0 + c]     = oacc[nt][0] * inv0;
        O[base0 + c + 1] = oacc[nt][1] * inv0;
        O[base1 + c]     = oacc[nt][2] * inv1;
        O[base1 + c + 1] = oacc[nt][3] * inv1;
    }
}

// ---------------- host orchestration ----------------
extern "C" void kernel_launch(void* const* d_in, const int* in_sizes, int n_in,
                              void* d_out, int out_size)
{
    const float* encoded = (const float*)d_in[0];
    const int*   seq     = (const int*)  d_in[1];
    const float* emb     = (const float*)d_in[2];
    const float* pos     = (const float*)d_in[3];
    const float* obias   = (const float*)d_in[4];
    const float* sa_qkv  = (const float*)d_in[5];
    const float* sa_o    = (const float*)d_in[6];
    const float* ca_q    = (const float*)d_in[7];
    const float* ca_kv   = (const float*)d_in[8];
    const float* ca_o    = (const float*)d_in[9];
    const float* ffn_w1  = (const float*)d_in[10];
    const float* ffn_b1  = (const float*)d_in[11];
    const float* ffn_w2  = (const float*)d_in[12];
    const float* ffn_b2  = (const float*)d_in[13];
    const float* ln_g    = (const float*)d_in[14];
    const float* ln_b    = (const float*)d_in[15];
    const float* fin_g   = (const float*)d_in[16];
    const float* fin_b   = (const float*)d_in[17];
    float* out = (float*)d_out;

    float *x, *q, *k, *v, *attn, *proj, *ffn;
    cudaGetSymbolAddress((void**)&x,    g_x);
    cudaGetSymbolAddress((void**)&q,    g_q);
    cudaGetSymbolAddress((void**)&k,    g_k);
    cudaGetSymbolAddress((void**)&v,    g_v);
    cudaGetSymbolAddress((void**)&attn, g_attn);
    cudaGetSymbolAddress((void**)&proj, g_proj);
    cudaGetSymbolAddress((void**)&ffn,  g_ffn);

    const int NQ = Bb * Ss;   // 8192
    const int NE = Bb * Mm;   // 16384
    const size_t DD = (size_t)Dd * Dd;

    dim3 gQKV (Dd/128, NQ/64, 3);
    dim3 gProj(Dd/128, NQ/64, 1);
    dim3 gCKV (Dd/128, NE/64, 2);
    dim3 gF1  (Ff/128, NQ/128, 1);
    dim3 gF2  (Dd/128, NQ/64, 1);
    dim3 gOut ((Vv + 127)/128, NQ/128, 1);
    dim3 gAttn(Ss/64, Bb*Hh);

    embed_kernel<<<NQ, 256>>>(seq, emb, pos, x);

    for (int i = 0; i < Ll; i++) {
        // ---- self attention ----
        gemm_tc<64,false,false><<<gQKV, 256>>>(x, sa_qkv + (size_t)i*3*DD, DD,
                                               nullptr, q, k, v, NQ, Dd, Dd);
        attn_tc<<<gAttn, 128>>>(q, k, v, attn, Ss, Ss, 1);
        gemm_tc<64,false,false><<<gProj, 256>>>(attn, sa_o + (size_t)i*DD, 0,
                                                nullptr, proj, nullptr, nullptr,
                                                NQ, Dd, Dd);
        ln_kernel<<<NQ, 256>>>(x, proj, ln_g + ((size_t)i*3 + 0)*Dd,
                               ln_b + ((size_t)i*3 + 0)*Dd, x);

        // ---- cross attention ----
        gemm_tc<64,false,false><<<gProj, 256>>>(x, ca_q + (size_t)i*DD, 0,
                                                nullptr, q, nullptr, nullptr,
                                                NQ, Dd, Dd);
        gemm_tc<64,false,false><<<gCKV, 256>>>(encoded, ca_kv + (size_t)i*2*DD, DD,
                                               nullptr, k, v, nullptr, NE, Dd, Dd);
        attn_tc<<<gAttn, 128>>>(q, k, v, attn, Ss, Mm, 0);
        gemm_tc<64,false,false><<<gProj, 256>>>(attn, ca_o + (size_t)i*DD, 0,
                                                nullptr, proj, nullptr, nullptr,
                                                NQ, Dd, Dd);
        ln_kernel<<<NQ, 256>>>(x, proj, ln_g + ((size_t)i*3 + 1)*Dd,
                               ln_b + ((size_t)i*3 + 1)*Dd, x);

        // ---- FFN ----
        gemm_tc<128,false,true ><<<gF1, 256>>>(x, ffn_w1 + (size_t)i*Dd*Ff, 0,
                                               ffn_b1 + (size_t)i*Ff, ffn,
                                               nullptr, nullptr, NQ, Ff, Dd);
        gemm_tc<64,false,false><<<gF2, 256>>>(ffn, ffn_w2 + (size_t)i*Ff*Dd, 0,
                                              ffn_b2 + (size_t)i*Dd, proj,
                                              nullptr, nullptr, NQ, Dd, Ff);
        ln_kernel<<<NQ, 256>>>(x, proj, ln_g + ((size_t)i*3 + 2)*Dd,
                               ln_b + ((size_t)i*3 + 2)*Dd, x);
    }

    ln_kernel<<<NQ, 256>>>(x, nullptr, fin_g, fin_b, x);
    gemm_tc<128,true,false><<<gOut, 256>>>(x, emb, 0, obias, out,
                                           nullptr, nullptr, NQ, Vv, Dd);
}

// round 14
// speedup vs baseline: 3.5244x; 1.0395x over previous
#include <cuda_runtime.h>
#include <cstdint>

#define Bb   16
#define Ss   512
#define Mm   1024
#define Dd   256
#define Hh   8
#define DHd  32
#define Ff   1024
#define Vv   3000
#define Ll   6

// ---------------- scratch (device globals; allocation-free) ----------------
__device__ float g_x   [Bb*Ss*Dd];
__device__ float g_q   [Bb*Ss*Dd];
__device__ float g_k   [Bb*Mm*Dd];
__device__ float g_v   [Bb*Mm*Dd];
__device__ float g_attn[Bb*Ss*Dd];
__device__ float g_proj[Bb*Ss*Dd];
__device__ float g_ffn [Bb*Ss*Ff];

// ---------------- embedding ----------------
__global__ void embed_kernel(const int* __restrict__ seq,
                             const float* __restrict__ emb,
                             const float* __restrict__ pos,
                             float* __restrict__ x)
{
    int row = blockIdx.x;
    int t   = threadIdx.x;
    int s   = row & (Ss - 1);
    int tok = seq[row];
    x[(size_t)row*Dd + t] = emb[(size_t)tok*Dd + t] + pos[(size_t)s*Dd + t];
}

// ---------------- add-residual + LayerNorm (warp-shuffle reduction) ----------------
__global__ void ln_kernel(const float* __restrict__ x, const float* __restrict__ r,
                          const float* __restrict__ g, const float* __restrict__ b,
                          float* __restrict__ y)
{
    __shared__ float red[8];
    int row = blockIdx.x, t = threadIdx.x;
    int warp = t >> 5, lane = t & 31;
    float v = x[(size_t)row*Dd + t];
    if (r) v += r[(size_t)row*Dd + t];

    float s = v;
    #pragma unroll
    for (int off = 16; off > 0; off >>= 1) s += __shfl_xor_sync(~0u, s, off);
    if (lane == 0) red[warp] = s;
    __syncthreads();
    float tot = 0.f;
    #pragma unroll
    for (int i = 0; i < 8; i++) tot += red[i];
    float mu = tot * (1.0f / Dd);
    __syncthreads();

    float dv = v - mu;
    s = dv * dv;
    #pragma unroll
    for (int off = 16; off > 0; off >>= 1) s += __shfl_xor_sync(~0u, s, off);
    if (lane == 0) red[warp] = s;
    __syncthreads();
    tot = 0.f;
    #pragma unroll
    for (int i = 0; i < 8; i++) tot += red[i];
    float var = tot * (1.0f / Dd);

    y[(size_t)row*Dd + t] = dv * rsqrtf(var + 1e-5f) * g[t] + b[t];
}

// ---------------- tf32 helpers ----------------
__device__ __forceinline__ uint32_t f2tf32(float x) {
    uint32_t y; asm("cvt.rna.tf32.f32 %0, %1;" : "=r"(y) : "f"(x)); return y;
}

__device__ __forceinline__ void mma_tf32(float* d, const uint32_t* a, const uint32_t* b) {
    asm volatile(
        "mma.sync.aligned.m16n8k8.row.col.f32.tf32.tf32.f32 "
        "{%0,%1,%2,%3}, {%4,%5,%6,%7}, {%8,%9}, {%0,%1,%2,%3};"
        : "+f"(d[0]), "+f"(d[1]), "+f"(d[2]), "+f"(d[3])
        : "r"(a[0]), "r"(a[1]), "r"(a[2]), "r"(a[3]), "r"(b[0]), "r"(b[1]));
}

// ---------------- tf32 tensor-core GEMM ----------------
// C = A @ B (+bias)(+relu).  A [M,K] row-major.
// TRANSB=false: B [K,N]; TRANSB=true: B [N,K] (C = A @ B^T).
// BM x 128 C tile, K-tile 32, 256 threads.
//   BM=64 : two-stage smem ping-pong, 1 barrier per k-tile (STS overlaps mma)
//   BM=128: single-stage, register double-buffered (reg-pressure bound)
// z=0 operand set: A0/B0/C0/M0.  z>0: A2, B2+(z-1)*bstride, C1/C2, M2
// (fuses QKV and crossQ+crossKV into single launches; blocks past M return early)
#define LDA 36      // 32 + 4 : A/NT-B fragment-read bank = 4*grp+th (conflict-free)
#define LDB 136     // 128 + 8: NN-B fragment-read bank = 8*th+grp (conflict-free)

template<int BM, bool TRANSB, bool RELU>
__global__ void __launch_bounds__(256)
gemm_tc(const float* __restrict__ A0, const float* __restrict__ B0,
        float* __restrict__ C0, int M0,
        const float* __restrict__ A2, const float* __restrict__ B2, size_t bstride,
        float* __restrict__ C1, float* __restrict__ C2, int M2,
        const float* __restrict__ bias, int N, int K)
{
    constexpr int NT    = (BM == 128) ? 4 : 2;     // 8-col n-tiles per warp
    constexpr int AREG  = BM / 32;                 // float4 per thread for A tile
    constexpr int BU    = TRANSB ? 128 * LDA : 32 * LDB;   // B stage size (u32)
    constexpr int STAGE = BM * LDA + BU;           // per-stage u32 count
    extern __shared__ uint32_t smemu[];

    int z = blockIdx.z;
    const float* A; const float* Bm; float* C; int M;
    if (z == 0) { A = A0; Bm = B0; C = C0; M = M0; }
    else { A = A2; Bm = B2 + (size_t)(z - 1) * bstride; C = (z == 1) ? C1 : C2; M = M2; }

    int m0 = blockIdx.y * BM;
    if (m0 >= M) return;                           // whole CTA exits (fused launches)
    int n0 = blockIdx.x * 128;

    int tid  = threadIdx.x;
    int warp = tid >> 5, lane = tid & 31;
    int wm = (BM == 128) ? (warp >> 2) : 0;
    int wn = (BM == 128) ? (warp & 3) : warp;
    int grp = lane >> 2, th = lane & 3;

    float4 ra[AREG], rb[4];

    auto load_tile = [&](int k0) {
        #pragma unroll
        for (int i = 0; i < AREG; i++) {
            int e = tid + i * 256;
            int r = e >> 3, c = (e & 7) * 4;
            ra[i] = *(const float4*)&A[(size_t)(m0 + r) * K + k0 + c];
        }
        if (TRANSB) {
            #pragma unroll
            for (int i = 0; i < 4; i++) {
                int e = tid + i * 256;
                int r = e >> 3, c = (e & 7) * 4;
                int n = n0 + r;
                rb[i] = (n < N) ? *(const float4*)&Bm[(size_t)n * K + k0 + c]
                                : make_float4(0.f, 0.f, 0.f, 0.f);
            }
        } else {
            #pragma unroll
            for (int i = 0; i < 4; i++) {
                int e = tid + i * 256;
                int r = e >> 5, c = (e & 31) * 4;
                rb[i] = *(const float4*)&Bm[(size_t)(k0 + r) * N + n0 + c];
            }
        }
    };

    auto store_stage = [&](int st) {
        uint32_t* As_ = smemu + st * STAGE;
        uint32_t* Bs_ = As_ + BM * LDA;
        #pragma unroll
        for (int i = 0; i < AREG; i++) {
            int e = tid + i * 256;
            int r = e >> 3, c = (e & 7) * 4;
            uint32_t* p = &As_[r * LDA + c];
            p[0] = f2tf32(ra[i].x); p[1] = f2tf32(ra[i].y);
            p[2] = f2tf32(ra[i].z); p[3] = f2tf32(ra[i].w);
        }
        #pragma unroll
        for (int i = 0; i < 4; i++) {
            int e = tid + i * 256;
            uint32_t* p;
            if (TRANSB) { int r = e >> 3, c = (e & 7) * 4;  p = &Bs_[r * LDA + c]; }
            else        { int r = e >> 5, c = (e & 31) * 4; p = &Bs_[r * LDB + c]; }
            p[0] = f2tf32(rb[i].x); p[1] = f2tf32(rb[i].y);
            p[2] = f2tf32(rb[i].z); p[3] = f2tf32(rb[i].w);
        }
    };

    float acc[4][NT][4] = {};

    auto mma_stage = [&](int st) {
        const uint32_t* As_ = smemu + st * STAGE;
        const uint32_t* Bs_ = As_ + BM * LDA;
        #pragma unroll
        for (int kk = 0; kk < 32; kk += 8) {
            uint32_t afr[4][4], bfr[NT][2];
            #pragma unroll
            for (int mt = 0; mt < 4; mt++) {
                int mr = (wm * 64 + mt * 16) * LDA + kk;
                afr[mt][0] = As_[mr + grp * LDA + th];
                afr[mt][1] = As_[mr + (grp + 8) * LDA + th];
                afr[mt][2] = As_[mr + grp * LDA + th + 4];
                afr[mt][3] = As_[mr + (grp + 8) * LDA + th + 4];
            }
            #pragma unroll
            for (int nt = 0; nt < NT; nt++) {
                int nc = wn * (8 * NT) + nt * 8 + grp;
                if (TRANSB) {
                    bfr[nt][0] = Bs_[nc * LDA + kk + th];
                    bfr[nt][1] = Bs_[nc * LDA + kk + th + 4];
                } else {
                    bfr[nt][0] = Bs_[(kk + th) * LDB + nc];
                    bfr[nt][1] = Bs_[(kk + th + 4) * LDB + nc];
                }
            }
            #pragma unroll
            for (int mt = 0; mt < 4; mt++)
                #pragma unroll
                for (int nt = 0; nt < NT; nt++)
                    mma_tf32(acc[mt][nt], afr[mt], bfr[nt]);
        }
    };

    if (BM == 64) {
        // ---- two-stage ping-pong: one barrier per k-tile ----
        load_tile(0);
        store_stage(0);
        __syncthreads();
        for (int k0 = 0; k0 < K; k0 += 32) {
            int st = (k0 >> 5) & 1;
            bool more = (k0 + 32 < K);
            if (more) load_tile(k0 + 32);     // LDG in flight across mma
            mma_stage(st);
            if (more) store_stage(st ^ 1);    // STS overlaps other warps' mma
            __syncthreads();
        }
    } else {
        // ---- single stage, register double buffer ----
        load_tile(0);
        for (int k0 = 0; k0 < K; k0 += 32) {
            store_stage(0);
            __syncthreads();
            if (k0 + 32 < K) load_tile(k0 + 32);
            mma_stage(0);
            __syncthreads();
        }
    }

    // ---- epilogue (paired stores; col even, 8B aligned) ----
    #pragma unroll
    for (int mt = 0; mt < 4; mt++) {
        int row0 = m0 + wm * 64 + mt * 16 + grp;
        #pragma unroll
        for (int nt = 0; nt < NT; nt++) {
            int col = n0 + wn * (8 * NT) + nt * 8 + th * 2;
            float bi0 = bias ? bias[min(col, N - 1)] : 0.f;
            float bi1 = bias ? bias[min(col + 1, N - 1)] : 0.f;
            #pragma unroll
            for (int half = 0; half < 2; half++) {
                int row = row0 + half * 8;
                float v0 = acc[mt][nt][half * 2 + 0] + bi0;
                float v1 = acc[mt][nt][half * 2 + 1] + bi1;
                if (RELU) { v0 = fmaxf(v0, 0.f); v1 = fmaxf(v1, 0.f); }
                if (col + 1 < N)
                    *(float2*)&C[(size_t)row * N + col] = make_float2(v0, v1);
                else if (col < N)
                    C[(size_t)row * N + col] = v0;
            }
        }
    }
}

// ---------------- tf32 flash attention (register double-buffered K/V) ----------------
#define LDQ 36
#define LDV 40
#define LDP 68

__global__ void __launch_bounds__(128)
attn_tc(const float* __restrict__ Q, const float* __restrict__ K,
        const float* __restrict__ V, float* __restrict__ O,
        int SqL, int SkvL, int causal)
{
    __shared__ uint32_t Qs[64 * LDQ];
    __shared__ uint32_t Ks[64 * LDQ];
    __shared__ uint32_t Vs[64 * LDV];
    __shared__ uint32_t Ps[64 * LDP];
    int tid = threadIdx.x;
    int warp = tid >> 5, lane = tid & 31;
    int grp = lane >> 2, th = lane & 3;
    int b = blockIdx.y >> 3, h = blockIdx.y & 7;
    int q0 = blockIdx.x * 64;
    const float scale = 0.17677669529663687f;   // 1/sqrt(32)

    #pragma unroll
    for (int i = 0; i < 4; i++) {
        int e = tid + i * 128;
        int r = e >> 3, c = (e & 7) * 4;
        float4 v = *(const float4*)&Q[((size_t)(b*SqL + q0 + r))*Dd + h*DHd + c];
        uint32_t* p = &Qs[r * LDQ + c];
        p[0] = f2tf32(v.x*scale); p[1] = f2tf32(v.y*scale);
        p[2] = f2tf32(v.z*scale); p[3] = f2tf32(v.w*scale);
    }

    float4 rk[4], rv[4];
    auto load_kv = [&](int kt) {
        int k0 = kt * 64;
        #pragma unroll
        for (int i = 0; i < 4; i++) {
            int e = tid + i * 128;
            int r = e >> 3, c = (e & 7) * 4;
            size_t gi = ((size_t)(b*SkvL + k0 + r))*Dd + h*DHd + c;
            rk[i] = *(const float4*)&K[gi];
            rv[i] = *(const float4*)&V[gi];
        }
    };

    float m0r = -1e30f, m1r = -1e30f, l0 = 0.f, l1 = 0.f;
    float oacc[4][4] = {};
    int prow0 = (warp*16 + grp) * LDP;
    int prow1 = (warp*16 + grp + 8) * LDP;

    int nkt = causal ? ((int)blockIdx.x + 1) : (SkvL >> 6);
    load_kv(0);
    for (int kt = 0; kt < nkt; kt++) {
        int k0 = kt * 64;
        __syncthreads();            // previous iter's Ks/Vs/Ps consumers done
        #pragma unroll
        for (int i = 0; i < 4; i++) {
            int e = tid + i * 128;
            int r = e >> 3, c = (e & 7) * 4;
            uint32_t* pk = &Ks[r * LDQ + c];
            pk[0] = f2tf32(rk[i].x); pk[1] = f2tf32(rk[i].y);
            pk[2] = f2tf32(rk[i].z); pk[3] = f2tf32(rk[i].w);
            uint32_t* pv = &Vs[r * LDV + c];
            pv[0] = f2tf32(rv[i].x); pv[1] = f2tf32(rv[i].y);
            pv[2] = f2tf32(rv[i].z); pv[3] = f2tf32(rv[i].w);
        }
        __syncthreads();
        if (kt + 1 < nkt) load_kv(kt + 1);   // in flight during S/softmax/PV

        // ---- S = Qs @ Ks^T : warp computes 16x64 ----
        float sacc[8][4] = {};
        #pragma unroll
        for (int kk = 0; kk < 32; kk += 8) {
            uint32_t afr[4];
            int mr = (warp*16) * LDQ + kk;
            afr[0] = Qs[mr + grp * LDQ + th];
            afr[1] = Qs[mr + (grp + 8) * LDQ + th];
            afr[2] = Qs[mr + grp * LDQ + th + 4];
            afr[3] = Qs[mr + (grp + 8) * LDQ + th + 4];
            #pragma unroll
            for (int nt = 0; nt < 8; nt++) {
                uint32_t bfr[2];
                int nc = nt * 8 + grp;
                bfr[0] = Ks[nc * LDQ + kk + th];
                bfr[1] = Ks[nc * LDQ + kk + th + 4];
                mma_tf32(sacc[nt], afr, bfr);
            }
        }

        if (causal && kt == (int)blockIdx.x) {
            int qg = q0 + warp*16 + grp;
            #pragma unroll
            for (int nt = 0; nt < 8; nt++) {
                int kv0 = k0 + nt*8 + 2*th;
                if (kv0     > qg)     sacc[nt][0] = -1e9f;
                if (kv0 + 1 > qg)     sacc[nt][1] = -1e9f;
                if (kv0     > qg + 8) sacc[nt][2] = -1e9f;
                if (kv0 + 1 > qg + 8) sacc[nt][3] = -1e9f;
            }
        }

        float rm0 = -1e30f, rm1 = -1e30f;
        #pragma unroll
        for (int nt = 0; nt < 8; nt++) {
            rm0 = fmaxf(rm0, fmaxf(sacc[nt][0], sacc[nt][1]));
            rm1 = fmaxf(rm1, fmaxf(sacc[nt][2], sacc[nt][3]));
        }
        rm0 = fmaxf(rm0, __shfl_xor_sync(0xffffffffu, rm0, 1));
        rm0 = fmaxf(rm0, __shfl_xor_sync(0xffffffffu, rm0, 2));
        rm1 = fmaxf(rm1, __shfl_xor_sync(0xffffffffu, rm1, 1));
        rm1 = fmaxf(rm1, __shfl_xor_sync(0xffffffffu, rm1, 2));
        float mn0 = fmaxf(m0r, rm0), mn1 = fmaxf(m1r, rm1);
        float a0 = __expf(m0r - mn0), a1 = __expf(m1r - mn1);
        float rs0 = 0.f, rs1 = 0.f;
        #pragma unroll
        for (int nt = 0; nt < 8; nt++) {
            float p0 = __expf(sacc[nt][0] - mn0);
            float p1 = __expf(sacc[nt][1] - mn0);
            float p2 = __expf(sacc[nt][2] - mn1);
            float p3 = __expf(sacc[nt][3] - mn1);
            rs0 += p0 + p1; rs1 += p2 + p3;
            int c = nt*8 + 2*th;
            *(uint2*)&Ps[prow0 + c] = make_uint2(f2tf32(p0), f2tf32(p1));
            *(uint2*)&Ps[prow1 + c] = make_uint2(f2tf32(p2), f2tf32(p3));
        }
        rs0 += __shfl_xor_sync(0xffffffffu, rs0, 1);
        rs0 += __shfl_xor_sync(0xffffffffu, rs0, 2);
        rs1 += __shfl_xor_sync(0xffffffffu, rs1, 1);
        rs1 += __shfl_xor_sync(0xffffffffu, rs1, 2);
        l0 = l0 * a0 + rs0; l1 = l1 * a1 + rs1;
        m0r = mn0; m1r = mn1;
        #pragma unroll
        for (int nt = 0; nt < 4; nt++) {
            oacc[nt][0] *= a0; oacc[nt][1] *= a0;
            oacc[nt][2] *= a1; oacc[nt][3] *= a1;
        }
        __syncwarp();               // Ps warp-private: order stores before loads

        #pragma unroll
        for (int kk = 0; kk < 64; kk += 8) {
            uint32_t afr[4];
            afr[0] = Ps[prow0 + kk + th];
            afr[1] = Ps[prow1 + kk + th];
            afr[2] = Ps[prow0 + kk + th + 4];
            afr[3] = Ps[prow1 + kk + th + 4];
            #pragma unroll
            for (int nt = 0; nt < 4; nt++) {
                uint32_t bfr[2];
                int nc = nt * 8 + grp;
                bfr[0] = Vs[(kk + th) * LDV + nc];
                bfr[1] = Vs[(kk + th + 4) * LDV + nc];
                mma_tf32(oacc[nt], afr, bfr);
            }
        }
    }

    float inv0 = 1.f / l0, inv1 = 1.f / l1;
    int qg = q0 + warp*16 + grp;
    size_t base0 = ((size_t)(b*SqL + qg    ))*Dd + h*DHd;
    size_t base1 = ((size_t)(b*SqL + qg + 8))*Dd + h*DHd;
    #pragma unroll
    for (int nt = 0; nt < 4; nt++) {
        int c = nt*8 + 2*th;
        O[base0 + c]     = oacc[nt][0] * inv0;
        O[base0 + c + 1] = oacc[nt][1] * inv0;
        O[base1 + c]     = oacc[nt][2] * inv1;
        O[base1 + c + 1] = oacc[nt][3] * inv1;
    }
}

// ---------------- host orchestration ----------------
extern "C" void kernel_launch(void* const* d_in, const int* in_sizes, int n_in,
                              void* d_out, int out_size)
{
    const float* encoded = (const float*)d_in[0];
    const int*   seq     = (const int*)  d_in[1];
    const float* emb     = (const float*)d_in[2];
    const float* pos     = (const float*)d_in[3];
    const float* obias   = (const float*)d_in[4];
    const float* sa_qkv  = (const float*)d_in[5];
    const float* sa_o    = (const float*)d_in[6];
    const float* ca_q    = (const float*)d_in[7];
    const float* ca_kv   = (const float*)d_in[8];
    const float* ca_o    = (const float*)d_in[9];
    const float* ffn_w1  = (const float*)d_in[10];
    const float* ffn_b1  = (const float*)d_in[11];
    const float* ffn_w2  = (const float*)d_in[12];
    const float* ffn_b2  = (const float*)d_in[13];
    const float* ln_g    = (const float*)d_in[14];
    const float* ln_b    = (const float*)d_in[15];
    const float* fin_g   = (const float*)d_in[16];
    const float* fin_b   = (const float*)d_in[17];
    float* out = (float*)d_out;

    float *x, *q, *k, *v, *attn, *proj, *ffn;
    cudaGetSymbolAddress((void**)&x,    g_x);
    cudaGetSymbolAddress((void**)&q,    g_q);
    cudaGetSymbolAddress((void**)&k,    g_k);
    cudaGetSymbolAddress((void**)&v,    g_v);
    cudaGetSymbolAddress((void**)&attn, g_attn);
    cudaGetSymbolAddress((void**)&proj, g_proj);
    cudaGetSymbolAddress((void**)&ffn,  g_ffn);

    const int NQ = Bb * Ss;   // 8192
    const int NE = Bb * Mm;   // 16384
    const size_t DD = (size_t)Dd * Dd;

    // dynamic smem sizes (bytes)
    const int SM64  = (64  * LDA + 32  * LDB) * 2 * 4;   // 53248 (two stages)
    const int SM128N = (128 * LDA + 32  * LDB) * 4;      // 35840 (NN)
    const int SM128T = (128 * LDA + 128 * LDA) * 4;      // 36864 (NT)

    static bool attr_done = false;
    if (!attr_done) {
        cudaFuncSetAttribute(gemm_tc<64,false,false>,
                             cudaFuncAttributeMaxDynamicSharedMemorySize, SM64);
        cudaFuncSetAttribute(gemm_tc<128,false,true>,
                             cudaFuncAttributeMaxDynamicSharedMemorySize, SM128N);
        cudaFuncSetAttribute(gemm_tc<128,true,false>,
                             cudaFuncAttributeMaxDynamicSharedMemorySize, SM128T);
        attr_done = true;
    }

    dim3 gQKV (Dd/128, NQ/64, 3);          // fused self q/k/v (768 CTAs)
    dim3 gCA  (Dd/128, NE/64, 3);          // fused cross q + k/v (z0 exits past NQ)
    dim3 gProj(Dd/128, NQ/64, 1);
    dim3 gF1  (Ff/128, NQ/128, 1);
    dim3 gF2  (Dd/128, NQ/64, 1);
    dim3 gOut ((Vv + 127)/128, NQ/128, 1);
    dim3 gAttn(Ss/64, Bb*Hh);

    embed_kernel<<<NQ, 256>>>(seq, emb, pos, x);

    for (int i = 0; i < Ll; i++) {
        const float* Wqkv = sa_qkv + (size_t)i*3*DD;

        // ---- self attention ----
        gemm_tc<64,false,false><<<gQKV, 256, SM64>>>(
            x, Wqkv, q, NQ,  x, Wqkv + DD, DD, k, v, NQ,  nullptr, Dd, Dd);
        attn_tc<<<gAttn, 128>>>(q, k, v, attn, Ss, Ss, 1);
        gemm_tc<64,false,false><<<gProj, 256, SM64>>>(
            attn, sa_o + (size_t)i*DD, proj, NQ,
            attn, sa_o + (size_t)i*DD, 0, proj, proj, 0, nullptr, Dd, Dd);
        ln_kernel<<<NQ, 256>>>(x, proj, ln_g + ((size_t)i*3 + 0)*Dd,
                               ln_b + ((size_t)i*3 + 0)*Dd, x);

        // ---- cross attention (q-proj fused with k/v-proj) ----
        gemm_tc<64,false,false><<<gCA, 256, SM64>>>(
            x, ca_q + (size_t)i*DD, q, NQ,
            encoded, ca_kv + (size_t)i*2*DD, DD, k, v, NE, nullptr, Dd, Dd);
        attn_tc<<<gAttn, 128>>>(q, k, v, attn, Ss, Mm, 0);
        gemm_tc<64,false,false><<<gProj, 256, SM64>>>(
            attn, ca_o + (size_t)i*DD, proj, NQ,
            attn, ca_o + (size_t)i*DD, 0, proj, proj, 0, nullptr, Dd, Dd);
        ln_kernel<<<NQ, 256>>>(x, proj, ln_g + ((size_t)i*3 + 1)*Dd,
                               ln_b + ((size_t)i*3 + 1)*Dd, x);

        // ---- FFN ----
        gemm_tc<128,false,true ><<<gF1, 256, SM128N>>>(
            x, ffn_w1 + (size_t)i*Dd*Ff, ffn, NQ,
            x, ffn_w1 + (size_t)i*Dd*Ff, 0, ffn, ffn, 0,
            ffn_b1 + (size_t)i*Ff, Ff, Dd);
        gemm_tc<64,false,false><<<gF2, 256, SM64>>>(
            ffn, ffn_w2 + (size_t)i*Ff*Dd, proj, NQ,
            ffn, ffn_w2 + (size_t)i*Ff*Dd, 0, proj, proj, 0,
            ffn_b2 + (size_t)i*Dd, Dd, Ff);
        ln_kernel<<<NQ, 256>>>(x, proj, ln_g + ((size_t)i*3 + 2)*Dd,
                               ln_b + ((size_t)i*3 + 2)*Dd, x);
    }

    ln_kernel<<<NQ, 256>>>(x, nullptr, fin_g, fin_b, x);
    gemm_tc<128,true,false><<<gOut, 256, SM128T>>>(
        x, emb, out, NQ,  x, emb, 0, out, out, 0,  obias, Vv, Dd);
}